// round 10
// baseline (speedup 1.0000x reference)
#include <cuda_runtime.h>
#include <math.h>
#include <stdint.h>

#define BB    2
#define TT    2048
#define DD    2048
#define HH    16
#define DK    128
#define N3    (3*DD)
#define MROWS (BB*TT)   // 4096

// ---------------- scratch (device globals; no allocation allowed) ----------------
__device__ float g_kqv[(size_t)MROWS * N3];    // fp32 k|q|v (tf32-rounded, rope applied)
__device__ float g_attn[(size_t)MROWS * DD];   // attention output fp32
__device__ float g_xp[(size_t)MROWS * DD];     // x packed (tf32)   [ck][M] float4 cells
__device__ float g_wkp[(size_t)DD * N3];       // Wkqv packed       [ck][N] float4 cells
__device__ float g_wop[(size_t)DD * DD];       // Wo packed
__device__ float g_ap[(size_t)MROWS * DD];     // attn packed
__device__ float4 g_kp[(size_t)32 * 32 * TT];    // K frag-packed: [bh][ck d-cell][key]
__device__ float4 g_vp[(size_t)32 * 512 * 128];  // V frag-packed: [bh][ckv key-cell][d]
__device__ float g_inv[64];
__device__ float g_cos[TT * 64];
__device__ float g_sin[TT * 64];

// ---------------- PTX helpers ----------------
__device__ __forceinline__ uint32_t smem_u32(const void* p) {
    return (uint32_t)__cvta_generic_to_shared(p);
}
__device__ __forceinline__ void cp16s(uint32_t dst, const void* src) {
    asm volatile("cp.async.cg.shared.global [%0], [%1], 16;\n" :: "r"(dst), "l"(src));
}
__device__ __forceinline__ void cp16(void* dst, const void* src) {
    asm volatile("cp.async.cg.shared.global [%0], [%1], 16;\n"
                 :: "r"(smem_u32(dst)), "l"(src));
}
__device__ __forceinline__ void cp_commit() {
    asm volatile("cp.async.commit_group;\n");
}
template<int N>
__device__ __forceinline__ void cp_wait() {
    asm volatile("cp.async.wait_group %0;\n" :: "n"(N));
}
__device__ __forceinline__ uint32_t f2tf(float f) {
    uint32_t r;
    asm("cvt.rna.tf32.f32 %0, %1;" : "=r"(r) : "f"(f));
    return r;
}
__device__ __forceinline__ float tfr(float f) {
    return __uint_as_float(f2tf(f));
}
__device__ __forceinline__ void mma_tf32(float c[4],
                                         uint32_t a0, uint32_t a1, uint32_t a2, uint32_t a3,
                                         uint32_t b0, uint32_t b1) {
    asm volatile(
        "mma.sync.aligned.m16n8k8.row.col.f32.tf32.tf32.f32 "
        "{%0,%1,%2,%3}, {%4,%5,%6,%7}, {%8,%9}, {%0,%1,%2,%3};\n"
        : "+f"(c[0]), "+f"(c[1]), "+f"(c[2]), "+f"(c[3])
        : "r"(a0), "r"(a1), "r"(a2), "r"(a3), "r"(b0), "r"(b1));
}
#define FU(x) __float_as_uint(x)

// ---------------- pack kernels: fragment-order gmem layout (GEMM) ----------------
__global__ void packA_kernel(const float* __restrict__ in, float4* __restrict__ out,
                             int Mt, int K)
{
    __shared__ float tile[32][65];
    const int k0 = blockIdx.x * 64;
    const int m0 = blockIdx.y * 32;
    const int t  = threadIdx.x;
    #pragma unroll
    for (int i = 0; i < 2; i++) {
        int u = t + (i << 8);
        int m = u >> 4;
        int kc = u & 15;
        float4 v = *(const float4*)&in[(size_t)(m0 + m) * K + k0 + kc * 4];
        tile[m][kc * 4 + 0] = v.x;
        tile[m][kc * 4 + 1] = v.y;
        tile[m][kc * 4 + 2] = v.z;
        tile[m][kc * 4 + 3] = v.w;
    }
    __syncthreads();
    #pragma unroll
    for (int i = 0; i < 2; i++) {
        int u  = t + (i << 8);
        int ck = u >> 5;
        int m  = u & 31;
        int kg = ck >> 2, tg = ck & 3;
        int kb = kg * 16 + tg;
        float4 v;
        v.x = tfr(tile[m][kb]);
        v.y = tfr(tile[m][kb + 4]);
        v.z = tfr(tile[m][kb + 8]);
        v.w = tfr(tile[m][kb + 12]);
        out[(size_t)((k0 / 16 + kg) * 4 + tg) * Mt + m0 + m] = v;
    }
}

__global__ void packB_kernel(const float* __restrict__ W, float4* __restrict__ out,
                             int K, int N)
{
    int idx = blockIdx.x * 256 + threadIdx.x;
    int total = (K / 4) * N;
    if (idx >= total) return;
    int ck = idx / N;
    int n  = idx - ck * N;
    int kg = ck >> 2, tg = ck & 3;
    int kb = kg * 16 + tg;
    float4 v;
    v.x = tfr(W[(size_t)kb * N + n]);
    v.y = tfr(W[(size_t)(kb + 4) * N + n]);
    v.z = tfr(W[(size_t)(kb + 8) * N + n]);
    v.w = tfr(W[(size_t)(kb + 12) * N + n]);
    out[(size_t)ck * N + n] = v;
}

// ---------------- pack K,V into attention fragment cells ----------------
// Kp[bh][ck][key]: ck = kg*4+tg over d; cell = K[key][kb], K[key][kb+4], K[key][kb+8], K[key][kb+12], kb = kg*16+tg
// Vp[bh][ckv][d]:  ckv = kgG*4+tgv over keys; cell = V[kbv][d], V[kbv+4][d], V[kbv+8][d], V[kbv+12][d], kbv = kgG*16+tgv
__global__ void pack_kv_kernel()
{
    __shared__ float kt_[32][132];
    __shared__ float vt_[32][132];
    const int bh = blockIdx.y;
    const int b  = bh >> 4;
    const int hoff = (bh & 15) * DK;
    const int k0 = blockIdx.x * 32;
    const int t  = threadIdx.x;

    #pragma unroll
    for (int i = 0; i < 4; i++) {
        int u   = t + (i << 8);        // 0..1023
        int key = u >> 5;              // 0..31
        int dc  = u & 31;              // f4 index 0..31
        const float* src = g_kqv + (size_t)(b * TT + k0 + key) * N3;
        *(float4*)&kt_[key][dc * 4] = *(const float4*)(src + hoff + dc * 4);
        *(float4*)&vt_[key][dc * 4] = *(const float4*)(src + 2 * DD + hoff + dc * 4);
    }
    __syncthreads();

    // K cells: 32 ck x 32 keys
    #pragma unroll
    for (int i = 0; i < 4; i++) {
        int u   = t + (i << 8);
        int ck  = u >> 5;
        int key = u & 31;
        int kb  = (ck >> 2) * 16 + (ck & 3);
        float4 o = make_float4(kt_[key][kb], kt_[key][kb + 4],
                               kt_[key][kb + 8], kt_[key][kb + 12]);
        g_kp[((size_t)bh * 32 + ck) * TT + k0 + key] = o;
    }
    // V cells: 8 local ckv x 128 d
    #pragma unroll
    for (int i = 0; i < 4; i++) {
        int u   = t + (i << 8);
        int cl  = u >> 7;              // 0..7
        int d   = u & 127;
        int kgl = cl >> 2, tgv = cl & 3;
        int kb  = kgl * 16 + tgv;      // local key base
        float4 o = make_float4(vt_[kb][d], vt_[kb + 4][d],
                               vt_[kb + 8][d], vt_[kb + 12][d]);
        int ckvG = (k0 / 16 + kgl) * 4 + tgv;
        g_vp[((size_t)bh * 512 + ckvG) * 128 + d] = o;
    }
}

// ---------------- packed TF32 GEMM: CTA 128x128, warp 64x32, BK=32/stage, 3 stages ----------------
#define HALF_CELLS  1040                     // 8*130
#define STAGE_BYTES (2 * HALF_CELLS * 16)    // 33280
#define GEMM_SMEM   (3 * STAGE_BYTES)        // 99840

__global__ __launch_bounds__(256, 2)
void gemm_packed_kernel(const float4* __restrict__ Ap, const float4* __restrict__ Bp,
                        const float* __restrict__ bias, float* __restrict__ C,
                        int Mt, int Nt, int K, int mode,
                        const float* __restrict__ ct, const float* __restrict__ st)
{
    extern __shared__ char smx[];
    const uint32_t sb = smem_u32(smx);
    const int t    = threadIdx.x;
    const int wid  = t >> 5;
    const int lane = t & 31;
    const int g    = lane >> 2;
    const int tg   = lane & 3;
    const int wm   = wid & 1;
    const int wn   = wid >> 1;
    const int rowBase = blockIdx.y * 128;
    const int colBase = blockIdx.x * 128;

    float acc[4][4][4];
    #pragma unroll
    for (int mi = 0; mi < 4; mi++)
        #pragma unroll
        for (int ni = 0; ni < 4; ni++)
            #pragma unroll
            for (int r = 0; r < 4; r++) acc[mi][ni][r] = 0.0f;

    const int NK = K / 32;

    auto issue = [&](int kt) {
        const uint32_t base = sb + (kt % 3) * STAGE_BYTES;
        #pragma unroll
        for (int i = 0; i < 8; i++) {
            const int u = t + (i << 8);
            if (u < 1024) {
                const int tg8 = u >> 7, mm = u & 127;
                cp16s(base + (tg8 * 130 + mm) * 16,
                      Ap + ((size_t)(kt * 8 + tg8) * Mt + rowBase + mm));
            } else {
                const int v = u - 1024;
                const int tg8 = v >> 7, mm = v & 127;
                cp16s(base + (HALF_CELLS + tg8 * 130 + mm) * 16,
                      Bp + ((size_t)(kt * 8 + tg8) * Nt + colBase + mm));
            }
        }
        cp_commit();
    };

    issue(0);
    issue(1);

    for (int kt = 0; kt < NK; kt++) {
        cp_wait<1>();
        __syncthreads();
        if (kt + 2 < NK) issue(kt + 2);

        const float* Stg = (const float*)(smx + (kt % 3) * STAGE_BYTES);

        #pragma unroll
        for (int sub = 0; sub < 2; sub++) {
            const float* Asl = Stg + (sub * 4 + tg) * 130 * 4;
            const float* Bsl = Stg + (HALF_CELLS + (sub * 4 + tg) * 130) * 4;

            float4 A0[4], A1[4], Bv[4];
            #pragma unroll
            for (int mi = 0; mi < 4; mi++) {
                const int mr = wm * 64 + mi * 16 + g;
                A0[mi] = *(const float4*)&Asl[mr * 4];
                A1[mi] = *(const float4*)&Asl[(mr + 8) * 4];
            }
            #pragma unroll
            for (int ni = 0; ni < 4; ni++)
                Bv[ni] = *(const float4*)&Bsl[(wn * 32 + ni * 8 + g) * 4];

            #pragma unroll
            for (int mi = 0; mi < 4; mi++)
                #pragma unroll
                for (int ni = 0; ni < 4; ni++) {
                    mma_tf32(acc[mi][ni], FU(A0[mi].x), FU(A1[mi].x), FU(A0[mi].y), FU(A1[mi].y),
                             FU(Bv[ni].x), FU(Bv[ni].y));
                    mma_tf32(acc[mi][ni], FU(A0[mi].z), FU(A1[mi].z), FU(A0[mi].w), FU(A1[mi].w),
                             FU(Bv[ni].z), FU(Bv[ni].w));
                }
        }
    }
    cp_wait<0>();

    // ---- epilogue: bias (+fused rope + tf32 rounding when mode==1) ----
    #pragma unroll
    for (int mi = 0; mi < 4; mi++) {
        const int r0 = rowBase + wm * 64 + mi * 16 + g;
        const int r1 = r0 + 8;
        #pragma unroll
        for (int ni = 0; ni < 4; ni++) {
            const int c = colBase + wn * 32 + ni * 8 + tg * 2;
            const float2 b2 = *(const float2*)&bias[c];
            float v0 = acc[mi][ni][0] + b2.x;
            float v1 = acc[mi][ni][1] + b2.y;
            float v2 = acc[mi][ni][2] + b2.x;
            float v3 = acc[mi][ni][3] + b2.y;
            if (mode == 1) {
                const int sect = c >> 11;
                if (sect < 2) {
                    const int pj = (c & 127) >> 1;
                    const float c0 = ct[(r0 & (TT - 1)) * 64 + pj];
                    const float s0 = st[(r0 & (TT - 1)) * 64 + pj];
                    const float c1 = ct[(r1 & (TT - 1)) * 64 + pj];
                    const float s1 = st[(r1 & (TT - 1)) * 64 + pj];
                    float e0 = v0 * c0 - v1 * s0, o0 = v0 * s0 + v1 * c0;
                    float e1 = v2 * c1 - v3 * s1, o1 = v2 * s1 + v3 * c1;
                    v0 = e0; v1 = o0; v2 = e1; v3 = o1;
                }
                v0 = tfr(v0); v1 = tfr(v1); v2 = tfr(v2); v3 = tfr(v3);
            }
            *(float2*)&C[(size_t)r0 * Nt + c] = make_float2(v0, v1);
            *(float2*)&C[(size_t)r1 * Nt + c] = make_float2(v2, v3);
        }
    }
}

// ---------------- RoPE tables ----------------
__global__ void freq_kernel(float* __restrict__ inv)
{
    int p = threadIdx.x;
    if (p < 64) inv[p] = (float)pow(10000.0, -(double)p / 64.0);
}

__global__ void trig_kernel(const float* __restrict__ inv,
                            float* __restrict__ ct, float* __restrict__ st)
{
    int idx = blockIdx.x * blockDim.x + threadIdx.x;
    if (idx >= TT * 64) return;
    int tpos = idx >> 6;
    int p    = idx & 63;
    float ang = (float)tpos * inv[p];
    float s, c;
    sincosf(ang, &s, &c);
    ct[idx] = c;
    st[idx] = s;
}

// ---------------- Flash attention (tf32 tensor cores, causal, frag-packed K/V) ----------------
// smem (floats): Ks [2][32][66 f4], Vs [2][16][130 f4], Ps [128][132]
#define KS_STF  (32 * 66 * 4)     // 8448 floats per stage
#define VS_STF  (16 * 130 * 4)    // 8320 floats per stage
#define VS_OFF  (2 * KS_STF)                  // 16896
#define PS_OFF  (VS_OFF + 2 * VS_STF)         // 33536
#define LDPK 132
#define ATT_SMEM ((PS_OFF + 128 * LDPK) * 4)  // 201728 B

__global__ __launch_bounds__(256, 1)
void attn_mma_kernel()
{
    extern __shared__ float sm[];
    float* Ps = sm + PS_OFF;

    const int t    = threadIdx.x;
    const int lane = t & 31;
    const int w    = t >> 5;
    const int g    = lane >> 2;
    const int tg   = lane & 3;
    const int bh = blockIdx.y;
    const int b  = bh >> 4;
    const int h  = bh & 15;
    const int qt = (int)gridDim.x - 1 - (int)blockIdx.x;
    const int qbase = qt * 128;
    const size_t rowbase = (size_t)b * TT;
    const int hoff = h * DK;
    const float scale = 0.08838834764831845f;

    // ---- stage Q tile, load fragments ----
    for (int u = t; u < 128 * 32; u += 256) {
        int qi = u >> 5;
        int c  = u & 31;
        float4 v = *(const float4*)&g_kqv[(rowbase + qbase + qi) * N3 + DD + hoff + c * 4];
        *(float4*)&Ps[qi * LDPK + c * 4] = v;
    }
    __syncthreads();
    const int qr = w * 16 + g;
    uint32_t qf[16][4];
    #pragma unroll
    for (int ks = 0; ks < 16; ks++) {
        qf[ks][0] = *(const uint32_t*)&Ps[qr * LDPK + ks * 8 + tg];
        qf[ks][1] = *(const uint32_t*)&Ps[(qr + 8) * LDPK + ks * 8 + tg];
        qf[ks][2] = *(const uint32_t*)&Ps[qr * LDPK + ks * 8 + tg + 4];
        qf[ks][3] = *(const uint32_t*)&Ps[(qr + 8) * LDPK + ks * 8 + tg + 4];
    }
    __syncthreads();

    float oacc[16][4];
    #pragma unroll
    for (int ni = 0; ni < 16; ni++)
        #pragma unroll
        for (int r = 0; r < 4; r++) oacc[ni][r] = 0.0f;
    float m0 = -1e30f, m1 = -1e30f, l0 = 0.0f, l1 = 0.0f;

    auto issue_tile = [&](int kt) {
        const int s = kt & 1;
        float* Kst = sm + s * KS_STF;
        float* Vst = sm + VS_OFF + s * VS_STF;
        #pragma unroll
        for (int i = 0; i < 8; i++) {          // K: 2048 cells
            int u = t + (i << 8);
            int r = u >> 6;                    // ck 0..31
            int c = u & 63;                    // key 0..63
            cp16(Kst + (r * 66 + c) * 4,
                 g_kp + ((size_t)bh * 32 + r) * TT + kt * 64 + c);
        }
        #pragma unroll
        for (int i = 0; i < 8; i++) {          // V: 2048 cells
            int u = t + (i << 8);
            int r = u >> 7;                    // ckv 0..15
            int c = u & 127;                   // d 0..127
            cp16(Vst + (r * 130 + c) * 4,
                 g_vp + ((size_t)bh * 512 + kt * 16 + r) * 128 + c);
        }
        cp_commit();
    };

    const int nkt = 2 * qt + 2;
    issue_tile(0);

    for (int kt = 0; kt < nkt; kt++) {
        const int s = kt & 1;
        __syncthreads();
        if (kt + 1 < nkt) issue_tile(kt + 1);
        cp_wait<1>();
        __syncthreads();

        float sacc[8][4];
        #pragma unroll
        for (int ni = 0; ni < 8; ni++)
            #pragma unroll
            for (int r = 0; r < 4; r++) sacc[ni][r] = 0.0f;

        // ---- S = Q @ K^T : LDS.128 fragments (one f4 covers 2 k-steps) ----
        const float4* Kb4 = (const float4*)(sm + s * KS_STF);
        #pragma unroll
        for (int kg = 0; kg < 8; kg++) {
            const float4* Krow = Kb4 + (kg * 4 + tg) * 66;
            #pragma unroll
            for (int ni = 0; ni < 8; ni++) {
                float4 bv = Krow[ni * 8 + g];
                mma_tf32(sacc[ni], qf[2 * kg][0], qf[2 * kg][1], qf[2 * kg][2], qf[2 * kg][3],
                         FU(bv.x), FU(bv.y));
                mma_tf32(sacc[ni], qf[2 * kg + 1][0], qf[2 * kg + 1][1], qf[2 * kg + 1][2], qf[2 * kg + 1][3],
                         FU(bv.z), FU(bv.w));
            }
        }

        const int r0 = qbase + w * 16 + g;
        const int r1 = r0 + 8;
        float rm0 = -1e30f, rm1 = -1e30f;
        if (kt >= 2 * qt) {
            const int kb = kt * 64;
            #pragma unroll
            for (int ni = 0; ni < 8; ni++) {
                const int c0 = kb + ni * 8 + 2 * tg;
                float v0 = sacc[ni][0] * scale; if (c0     > r0) v0 = -1e30f;
                float v1 = sacc[ni][1] * scale; if (c0 + 1 > r0) v1 = -1e30f;
                float v2 = sacc[ni][2] * scale; if (c0     > r1) v2 = -1e30f;
                float v3 = sacc[ni][3] * scale; if (c0 + 1 > r1) v3 = -1e30f;
                sacc[ni][0] = v0; sacc[ni][1] = v1; sacc[ni][2] = v2; sacc[ni][3] = v3;
                rm0 = fmaxf(rm0, fmaxf(v0, v1));
                rm1 = fmaxf(rm1, fmaxf(v2, v3));
            }
        } else {
            #pragma unroll
            for (int ni = 0; ni < 8; ni++) {
                float v0 = sacc[ni][0] * scale;
                float v1 = sacc[ni][1] * scale;
                float v2 = sacc[ni][2] * scale;
                float v3 = sacc[ni][3] * scale;
                sacc[ni][0] = v0; sacc[ni][1] = v1; sacc[ni][2] = v2; sacc[ni][3] = v3;
                rm0 = fmaxf(rm0, fmaxf(v0, v1));
                rm1 = fmaxf(rm1, fmaxf(v2, v3));
            }
        }
        rm0 = fmaxf(rm0, __shfl_xor_sync(0xffffffffu, rm0, 1));
        rm0 = fmaxf(rm0, __shfl_xor_sync(0xffffffffu, rm0, 2));
        rm1 = fmaxf(rm1, __shfl_xor_sync(0xffffffffu, rm1, 1));
        rm1 = fmaxf(rm1, __shfl_xor_sync(0xffffffffu, rm1, 2));

        const float mn0 = fmaxf(m0, rm0);
        const float mn1 = fmaxf(m1, rm1);
        const float f0 = __expf(m0 - mn0);
        const float f1 = __expf(m1 - mn1);
        m0 = mn0; m1 = mn1;

        float ps0 = 0.0f, ps1 = 0.0f;
        #pragma unroll
        for (int ni = 0; ni < 8; ni++) {
            float p0 = __expf(sacc[ni][0] - mn0);
            float p1 = __expf(sacc[ni][1] - mn0);
            float p2 = __expf(sacc[ni][2] - mn1);
            float p3 = __expf(sacc[ni][3] - mn1);
            sacc[ni][0] = p0; sacc[ni][1] = p1; sacc[ni][2] = p2; sacc[ni][3] = p3;
            ps0 += p0 + p1;
            ps1 += p2 + p3;
        }
        ps0 += __shfl_xor_sync(0xffffffffu, ps0, 1);
        ps0 += __shfl_xor_sync(0xffffffffu, ps0, 2);
        ps1 += __shfl_xor_sync(0xffffffffu, ps1, 1);
        ps1 += __shfl_xor_sync(0xffffffffu, ps1, 2);
        l0 = l0 * f0 + ps0;
        l1 = l1 * f1 + ps1;

        #pragma unroll
        for (int ni = 0; ni < 16; ni++) {
            oacc[ni][0] *= f0; oacc[ni][1] *= f0;
            oacc[ni][2] *= f1; oacc[ni][3] *= f1;
        }

        const int pq = w * 16 + g;
        #pragma unroll
        for (int ni = 0; ni < 8; ni++) {
            *(float2*)&Ps[pq * LDPK + ni * 8 + 2 * tg]       = make_float2(sacc[ni][0], sacc[ni][1]);
            *(float2*)&Ps[(pq + 8) * LDPK + ni * 8 + 2 * tg] = make_float2(sacc[ni][2], sacc[ni][3]);
        }
        __syncwarp();   // P rows are warp-private

        // ---- O += P @ V : LDS.128 fragments ----
        const float4* Vb4 = (const float4*)(sm + VS_OFF + s * VS_STF);
        #pragma unroll
        for (int kg2 = 0; kg2 < 4; kg2++) {
            uint32_t ha[2][4];
            #pragma unroll
            for (int hh = 0; hh < 2; hh++) {
                const int ks2 = 2 * kg2 + hh;
                ha[hh][0] = f2tf(Ps[pq * LDPK + ks2 * 8 + tg]);
                ha[hh][1] = f2tf(Ps[(pq + 8) * LDPK + ks2 * 8 + tg]);
                ha[hh][2] = f2tf(Ps[pq * LDPK + ks2 * 8 + tg + 4]);
                ha[hh][3] = f2tf(Ps[(pq + 8) * LDPK + ks2 * 8 + tg + 4]);
            }
            const float4* Vrow = Vb4 + (kg2 * 4 + tg) * 130;
            #pragma unroll
            for (int ni = 0; ni < 16; ni++) {
                float4 vv = Vrow[ni * 8 + g];
                mma_tf32(oacc[ni], ha[0][0], ha[0][1], ha[0][2], ha[0][3], FU(vv.x), FU(vv.y));
                mma_tf32(oacc[ni], ha[1][0], ha[1][1], ha[1][2], ha[1][3], FU(vv.z), FU(vv.w));
            }
        }
    }

    // ---- epilogue: O / l -> g_attn fp32 ----
    const float il0 = 1.0f / l0;
    const float il1 = 1.0f / l1;
    const size_t row0 = rowbase + qbase + w * 16 + g;
    #pragma unroll
    for (int ni = 0; ni < 16; ni++) {
        const int col = hoff + ni * 8 + 2 * tg;
        *(float2*)&g_attn[row0 * DD + col] =
            make_float2(oacc[ni][0] * il0, oacc[ni][1] * il0);
        *(float2*)&g_attn[(row0 + 8) * DD + col] =
            make_float2(oacc[ni][2] * il1, oacc[ni][3] * il1);
    }
}

// ---------------- launch ----------------
extern "C" void kernel_launch(void* const* d_in, const int* in_sizes, int n_in,
                              void* d_out, int out_size)
{
    const float* x    = (const float*)d_in[0];
    const float* Wkqv = (const float*)d_in[1];
    const float* bkqv = (const float*)d_in[2];
    const float* Wo   = (const float*)d_in[3];
    const float* bo   = (const float*)d_in[4];
    float* out = (float*)d_out;

    float *kqv, *attn, *xp, *wkp, *wop, *ap, *inv, *ct, *st;
    cudaGetSymbolAddress((void**)&kqv, g_kqv);
    cudaGetSymbolAddress((void**)&attn, g_attn);
    cudaGetSymbolAddress((void**)&xp,  g_xp);
    cudaGetSymbolAddress((void**)&wkp, g_wkp);
    cudaGetSymbolAddress((void**)&wop, g_wop);
    cudaGetSymbolAddress((void**)&ap,  g_ap);
    cudaGetSymbolAddress((void**)&inv, g_inv);
    cudaGetSymbolAddress((void**)&ct,  g_cos);
    cudaGetSymbolAddress((void**)&st,  g_sin);

    cudaFuncSetAttribute(gemm_packed_kernel, cudaFuncAttributeMaxDynamicSharedMemorySize, GEMM_SMEM);
    cudaFuncSetAttribute(attn_mma_kernel,    cudaFuncAttributeMaxDynamicSharedMemorySize, ATT_SMEM);

    // 0) rope tables + pack operands (tf32 rna rounding folded in)
    freq_kernel<<<1, 64>>>(inv);
    trig_kernel<<<(TT * 64) / 256, 256>>>(inv, ct, st);
    packA_kernel<<<dim3(DD / 64, MROWS / 32), 256>>>(x, (float4*)xp, MROWS, DD);
    packB_kernel<<<(DD / 4 * N3 + 255) / 256, 256>>>(Wkqv, (float4*)wkp, DD, N3);
    packB_kernel<<<(DD / 4 * DD + 255) / 256, 256>>>(Wo, (float4*)wop, DD, DD);

    // 1) kqv = x @ Wkqv + bkqv, fused rope + tf32 rounding
    gemm_packed_kernel<<<dim3(N3 / 128, MROWS / 128), 256, GEMM_SMEM>>>(
        (const float4*)xp, (const float4*)wkp, bkqv, kqv, MROWS, N3, DD, 1, ct, st);

    // 1b) pack K,V into attention fragment cells
    pack_kv_kernel<<<dim3(TT / 32, BB * HH), 256>>>();

    // 2) causal flash attention -> g_attn
    attn_mma_kernel<<<dim3(TT / 128, BB * HH), 256, ATT_SMEM>>>();

    // 3) pack attention output, then out = attn @ Wo + bo
    packA_kernel<<<dim3(DD / 64, MROWS / 32), 256>>>(attn, (float4*)ap, MROWS, DD);
    gemm_packed_kernel<<<dim3(DD / 128, MROWS / 128), 256, GEMM_SMEM>>>(
        (const float4*)ap, (const float4*)wop, bo, out, MROWS, DD, DD, 0, ct, st);
}

// round 11
// speedup vs baseline: 1.0040x; 1.0040x over previous
#include <cuda_runtime.h>
#include <math.h>
#include <stdint.h>

#define BB    2
#define TT    2048
#define DD    2048
#define HH    16
#define DK    128
#define N3    (3*DD)
#define MROWS (BB*TT)   // 4096

// ---------------- scratch (device globals; no allocation allowed) ----------------
__device__ float g_kqv[(size_t)MROWS * N3];    // fp32 k|q|v (tf32-rounded, rope applied)
__device__ float g_attn[(size_t)MROWS * DD];   // attention output fp32
__device__ float g_xp[(size_t)MROWS * DD];     // x packed (tf32)   [ck][M] float4 cells
__device__ float g_wkp[(size_t)DD * N3];       // Wkqv packed       [ck][N] float4 cells
__device__ float g_wop[(size_t)DD * DD];       // Wo packed
__device__ float g_ap[(size_t)MROWS * DD];     // attn packed
__device__ float4 g_kp[(size_t)32 * 32 * TT];    // K frag-packed: [bh][ck d-cell][key]
__device__ float4 g_vp[(size_t)32 * 512 * 128];  // V frag-packed: [bh][ckv key-cell][d]
__device__ float g_cos[TT * 64];
__device__ float g_sin[TT * 64];

// ---------------- PTX helpers ----------------
__device__ __forceinline__ uint32_t smem_u32(const void* p) {
    return (uint32_t)__cvta_generic_to_shared(p);
}
__device__ __forceinline__ void cp16s(uint32_t dst, const void* src) {
    asm volatile("cp.async.cg.shared.global [%0], [%1], 16;\n" :: "r"(dst), "l"(src));
}
__device__ __forceinline__ void cp16(void* dst, const void* src) {
    asm volatile("cp.async.cg.shared.global [%0], [%1], 16;\n"
                 :: "r"(smem_u32(dst)), "l"(src));
}
__device__ __forceinline__ void cp_commit() {
    asm volatile("cp.async.commit_group;\n");
}
template<int N>
__device__ __forceinline__ void cp_wait() {
    asm volatile("cp.async.wait_group %0;\n" :: "n"(N));
}
__device__ __forceinline__ uint32_t f2tf(float f) {
    uint32_t r;
    asm("cvt.rna.tf32.f32 %0, %1;" : "=r"(r) : "f"(f));
    return r;
}
__device__ __forceinline__ float tfr(float f) {
    return __uint_as_float(f2tf(f));
}
__device__ __forceinline__ void mma_tf32(float c[4],
                                         uint32_t a0, uint32_t a1, uint32_t a2, uint32_t a3,
                                         uint32_t b0, uint32_t b1) {
    asm volatile(
        "mma.sync.aligned.m16n8k8.row.col.f32.tf32.tf32.f32 "
        "{%0,%1,%2,%3}, {%4,%5,%6,%7}, {%8,%9}, {%0,%1,%2,%3};\n"
        : "+f"(c[0]), "+f"(c[1]), "+f"(c[2]), "+f"(c[3])
        : "r"(a0), "r"(a1), "r"(a2), "r"(a3), "r"(b0), "r"(b1));
}
#define FU(x) __float_as_uint(x)

// ---------------- RoPE trig tables (freq folded in) ----------------
__global__ void trig_kernel(float* __restrict__ ct, float* __restrict__ st)
{
    int idx = blockIdx.x * blockDim.x + threadIdx.x;
    if (idx >= TT * 64) return;
    int tpos = idx >> 6;
    int p    = idx & 63;
    float invf = (float)pow(10000.0, -(double)p / 64.0);
    float ang = (float)tpos * invf;
    float s, c;
    sincosf(ang, &s, &c);
    ct[idx] = c;
    st[idx] = s;
}

// ---------------- pack kernels: fragment-order gmem layout (GEMM) ----------------
__global__ void packA_kernel(const float* __restrict__ in, float4* __restrict__ out,
                             int Mt, int K)
{
    __shared__ float tile[32][65];
    const int k0 = blockIdx.x * 64;
    const int m0 = blockIdx.y * 32;
    const int t  = threadIdx.x;
    #pragma unroll
    for (int i = 0; i < 2; i++) {
        int u = t + (i << 8);
        int m = u >> 4;
        int kc = u & 15;
        float4 v = *(const float4*)&in[(size_t)(m0 + m) * K + k0 + kc * 4];
        tile[m][kc * 4 + 0] = v.x;
        tile[m][kc * 4 + 1] = v.y;
        tile[m][kc * 4 + 2] = v.z;
        tile[m][kc * 4 + 3] = v.w;
    }
    __syncthreads();
    #pragma unroll
    for (int i = 0; i < 2; i++) {
        int u  = t + (i << 8);
        int ck = u >> 5;
        int m  = u & 31;
        int kg = ck >> 2, tg = ck & 3;
        int kb = kg * 16 + tg;
        float4 v;
        v.x = tfr(tile[m][kb]);
        v.y = tfr(tile[m][kb + 4]);
        v.z = tfr(tile[m][kb + 8]);
        v.w = tfr(tile[m][kb + 12]);
        out[(size_t)((k0 / 16 + kg) * 4 + tg) * Mt + m0 + m] = v;
    }
}

__global__ void packB_kernel(const float* __restrict__ W, float4* __restrict__ out,
                             int K, int N)
{
    int idx = blockIdx.x * 256 + threadIdx.x;
    int total = (K / 4) * N;
    if (idx >= total) return;
    int ck = idx / N;
    int n  = idx - ck * N;
    int kg = ck >> 2, tg = ck & 3;
    int kb = kg * 16 + tg;
    float4 v;
    v.x = tfr(W[(size_t)kb * N + n]);
    v.y = tfr(W[(size_t)(kb + 4) * N + n]);
    v.z = tfr(W[(size_t)(kb + 8) * N + n]);
    v.w = tfr(W[(size_t)(kb + 12) * N + n]);
    out[(size_t)ck * N + n] = v;
}

// ---------------- pack K,V into attention fragment cells ----------------
__global__ void pack_kv_kernel()
{
    __shared__ float kt_[32][132];
    __shared__ float vt_[32][132];
    const int bh = blockIdx.y;
    const int b  = bh >> 4;
    const int hoff = (bh & 15) * DK;
    const int k0 = blockIdx.x * 32;
    const int t  = threadIdx.x;

    #pragma unroll
    for (int i = 0; i < 4; i++) {
        int u   = t + (i << 8);
        int key = u >> 5;
        int dc  = u & 31;
        const float* src = g_kqv + (size_t)(b * TT + k0 + key) * N3;
        *(float4*)&kt_[key][dc * 4] = *(const float4*)(src + hoff + dc * 4);
        *(float4*)&vt_[key][dc * 4] = *(const float4*)(src + 2 * DD + hoff + dc * 4);
    }
    __syncthreads();

    #pragma unroll
    for (int i = 0; i < 4; i++) {
        int u   = t + (i << 8);
        int ck  = u >> 5;
        int key = u & 31;
        int kb  = (ck >> 2) * 16 + (ck & 3);
        float4 o = make_float4(kt_[key][kb], kt_[key][kb + 4],
                               kt_[key][kb + 8], kt_[key][kb + 12]);
        g_kp[((size_t)bh * 32 + ck) * TT + k0 + key] = o;
    }
    #pragma unroll
    for (int i = 0; i < 4; i++) {
        int u   = t + (i << 8);
        int cl  = u >> 7;
        int d   = u & 127;
        int kgl = cl >> 2, tgv = cl & 3;
        int kb  = kgl * 16 + tgv;
        float4 o = make_float4(vt_[kb][d], vt_[kb + 4][d],
                               vt_[kb + 8][d], vt_[kb + 12][d]);
        int ckvG = (k0 / 16 + kgl) * 4 + tgv;
        g_vp[((size_t)bh * 512 + ckvG) * 128 + d] = o;
    }
}

// ---------------- packed TF32 GEMM: CTA 128x128, warp 64x32, BK=32/stage, 3 stages ----------------
#define HALF_CELLS  1040                     // 8*130
#define STAGE_BYTES (2 * HALF_CELLS * 16)    // 33280
#define GEMM_SMEM   (3 * STAGE_BYTES)        // 99840

__global__ __launch_bounds__(256, 2)
void gemm_packed_kernel(const float4* __restrict__ Ap, const float4* __restrict__ Bp,
                        const float* __restrict__ bias, float* __restrict__ C,
                        int Mt, int Nt, int K, int mode,
                        const float* __restrict__ ct, const float* __restrict__ st)
{
    extern __shared__ char smx[];
    const uint32_t sb = smem_u32(smx);
    const int t    = threadIdx.x;
    const int wid  = t >> 5;
    const int lane = t & 31;
    const int g    = lane >> 2;
    const int tg   = lane & 3;
    const int wm   = wid & 1;
    const int wn   = wid >> 1;
    const int rowBase = blockIdx.y * 128;
    const int colBase = blockIdx.x * 128;

    float acc[4][4][4];
    #pragma unroll
    for (int mi = 0; mi < 4; mi++)
        #pragma unroll
        for (int ni = 0; ni < 4; ni++)
            #pragma unroll
            for (int r = 0; r < 4; r++) acc[mi][ni][r] = 0.0f;

    const int NK = K / 32;

    auto issue = [&](int kt) {
        const uint32_t base = sb + (kt % 3) * STAGE_BYTES;
        #pragma unroll
        for (int i = 0; i < 8; i++) {
            const int u = t + (i << 8);
            if (u < 1024) {
                const int tg8 = u >> 7, mm = u & 127;
                cp16s(base + (tg8 * 130 + mm) * 16,
                      Ap + ((size_t)(kt * 8 + tg8) * Mt + rowBase + mm));
            } else {
                const int v = u - 1024;
                const int tg8 = v >> 7, mm = v & 127;
                cp16s(base + (HALF_CELLS + tg8 * 130 + mm) * 16,
                      Bp + ((size_t)(kt * 8 + tg8) * Nt + colBase + mm));
            }
        }
        cp_commit();
    };

    issue(0);
    issue(1);

    for (int kt = 0; kt < NK; kt++) {
        cp_wait<1>();
        __syncthreads();
        if (kt + 2 < NK) issue(kt + 2);

        const float* Stg = (const float*)(smx + (kt % 3) * STAGE_BYTES);

        #pragma unroll
        for (int sub = 0; sub < 2; sub++) {
            const float* Asl = Stg + (sub * 4 + tg) * 130 * 4;
            const float* Bsl = Stg + (HALF_CELLS + (sub * 4 + tg) * 130) * 4;

            float4 A0[4], A1[4], Bv[4];
            #pragma unroll
            for (int mi = 0; mi < 4; mi++) {
                const int mr = wm * 64 + mi * 16 + g;
                A0[mi] = *(const float4*)&Asl[mr * 4];
                A1[mi] = *(const float4*)&Asl[(mr + 8) * 4];
            }
            #pragma unroll
            for (int ni = 0; ni < 4; ni++)
                Bv[ni] = *(const float4*)&Bsl[(wn * 32 + ni * 8 + g) * 4];

            #pragma unroll
            for (int mi = 0; mi < 4; mi++)
                #pragma unroll
                for (int ni = 0; ni < 4; ni++) {
                    mma_tf32(acc[mi][ni], FU(A0[mi].x), FU(A1[mi].x), FU(A0[mi].y), FU(A1[mi].y),
                             FU(Bv[ni].x), FU(Bv[ni].y));
                    mma_tf32(acc[mi][ni], FU(A0[mi].z), FU(A1[mi].z), FU(A0[mi].w), FU(A1[mi].w),
                             FU(Bv[ni].z), FU(Bv[ni].w));
                }
        }
    }
    cp_wait<0>();

    // ---- epilogue: bias (+fused rope + tf32 rounding when mode==1) ----
    #pragma unroll
    for (int mi = 0; mi < 4; mi++) {
        const int r0 = rowBase + wm * 64 + mi * 16 + g;
        const int r1 = r0 + 8;
        #pragma unroll
        for (int ni = 0; ni < 4; ni++) {
            const int c = colBase + wn * 32 + ni * 8 + tg * 2;
            const float2 b2 = *(const float2*)&bias[c];
            float v0 = acc[mi][ni][0] + b2.x;
            float v1 = acc[mi][ni][1] + b2.y;
            float v2 = acc[mi][ni][2] + b2.x;
            float v3 = acc[mi][ni][3] + b2.y;
            if (mode == 1) {
                const int sect = c >> 11;
                if (sect < 2) {
                    const int pj = (c & 127) >> 1;
                    const float c0 = ct[(r0 & (TT - 1)) * 64 + pj];
                    const float s0 = st[(r0 & (TT - 1)) * 64 + pj];
                    const float c1 = ct[(r1 & (TT - 1)) * 64 + pj];
                    const float s1 = st[(r1 & (TT - 1)) * 64 + pj];
                    float e0 = v0 * c0 - v1 * s0, o0 = v0 * s0 + v1 * c0;
                    float e1 = v2 * c1 - v3 * s1, o1 = v2 * s1 + v3 * c1;
                    v0 = e0; v1 = o0; v2 = e1; v3 = o1;
                }
                v0 = tfr(v0); v1 = tfr(v1); v2 = tfr(v2); v3 = tfr(v3);
            }
            *(float2*)&C[(size_t)r0 * Nt + c] = make_float2(v0, v1);
            *(float2*)&C[(size_t)r1 * Nt + c] = make_float2(v2, v3);
        }
    }
}

// ---------------- Flash attention: 64q CTAs, 128 thr, 32-key tiles, 2 CTAs/SM ----------------
// smem (floats): Ks [2][32][34 f4], Vs [2][8][130 f4], Ps [64][132]
#define A_KS_STF (32 * 34 * 4)               // 4352 floats/stage
#define A_VS_STF (8 * 130 * 4)               // 4160 floats/stage
#define A_VS_OFF (2 * A_KS_STF)              // 8704
#define A_PS_OFF (A_VS_OFF + 2 * A_VS_STF)   // 17024
#define LDPK 132
#define ATT_SMEM ((A_PS_OFF + 64 * LDPK) * 4)   // 101888 B -> 2 CTAs/SM

__global__ __launch_bounds__(128, 2)
void attn_mma_kernel()
{
    extern __shared__ float sm[];
    float* Ps = sm + A_PS_OFF;

    const int t    = threadIdx.x;
    const int lane = t & 31;
    const int w    = t >> 5;       // 0..3
    const int g    = lane >> 2;
    const int tg   = lane & 3;
    const int bh = blockIdx.y;
    const int b  = bh >> 4;
    const int h  = bh & 15;
    const int qt = (int)gridDim.x - 1 - (int)blockIdx.x;   // heavy first, 0..31
    const int qbase = qt * 64;
    const size_t rowbase = (size_t)b * TT;
    const int hoff = h * DK;
    const float scale = 0.08838834764831845f;

    // ---- stage Q tile (64 rows), load fragments ----
    for (int u = t; u < 64 * 32; u += 128) {
        int qi = u >> 5;
        int c  = u & 31;
        float4 v = *(const float4*)&g_kqv[(rowbase + qbase + qi) * N3 + DD + hoff + c * 4];
        *(float4*)&Ps[qi * LDPK + c * 4] = v;
    }
    __syncthreads();
    const int qr = w * 16 + g;
    uint32_t qf[16][4];
    #pragma unroll
    for (int ks = 0; ks < 16; ks++) {
        qf[ks][0] = *(const uint32_t*)&Ps[qr * LDPK + ks * 8 + tg];
        qf[ks][1] = *(const uint32_t*)&Ps[(qr + 8) * LDPK + ks * 8 + tg];
        qf[ks][2] = *(const uint32_t*)&Ps[qr * LDPK + ks * 8 + tg + 4];
        qf[ks][3] = *(const uint32_t*)&Ps[(qr + 8) * LDPK + ks * 8 + tg + 4];
    }
    __syncthreads();

    float oacc[16][4];
    #pragma unroll
    for (int ni = 0; ni < 16; ni++)
        #pragma unroll
        for (int r = 0; r < 4; r++) oacc[ni][r] = 0.0f;
    float m0 = -1e30f, m1 = -1e30f, l0 = 0.0f, l1 = 0.0f;

    auto issue_tile = [&](int kt) {
        const int s = kt & 1;
        float* Kst = sm + s * A_KS_STF;
        float* Vst = sm + A_VS_OFF + s * A_VS_STF;
        #pragma unroll
        for (int i = 0; i < 8; i++) {          // K: 1024 cells (32 ck x 32 keys)
            int u = t + (i << 7);
            int r = u >> 5;
            int c = u & 31;
            cp16(Kst + (r * 34 + c) * 4,
                 g_kp + ((size_t)bh * 32 + r) * TT + kt * 32 + c);
        }
        #pragma unroll
        for (int i = 0; i < 8; i++) {          // V: 1024 cells (8 ckv x 128 d)
            int u = t + (i << 7);
            int r = u >> 7;
            int c = u & 127;
            cp16(Vst + (r * 130 + c) * 4,
                 g_vp + ((size_t)bh * 512 + kt * 8 + r) * 128 + c);
        }
        cp_commit();
    };

    const int nkt = 2 * qt + 2;   // 32-key tiles covering keys < 64*(qt+1)
    issue_tile(0);

    for (int kt = 0; kt < nkt; kt++) {
        const int s = kt & 1;
        __syncthreads();
        if (kt + 1 < nkt) issue_tile(kt + 1);
        cp_wait<1>();
        __syncthreads();

        float sacc[4][4];
        #pragma unroll
        for (int ni = 0; ni < 4; ni++)
            #pragma unroll
            for (int r = 0; r < 4; r++) sacc[ni][r] = 0.0f;

        // ---- S = Q @ K^T ----
        const float4* Kb4 = (const float4*)(sm + s * A_KS_STF);
        #pragma unroll
        for (int kg = 0; kg < 8; kg++) {
            const float4* Krow = Kb4 + (kg * 4 + tg) * 34;
            #pragma unroll
            for (int ni = 0; ni < 4; ni++) {
                float4 bv = Krow[ni * 8 + g];
                mma_tf32(sacc[ni], qf[2 * kg][0], qf[2 * kg][1], qf[2 * kg][2], qf[2 * kg][3],
                         FU(bv.x), FU(bv.y));
                mma_tf32(sacc[ni], qf[2 * kg + 1][0], qf[2 * kg + 1][1], qf[2 * kg + 1][2], qf[2 * kg + 1][3],
                         FU(bv.z), FU(bv.w));
            }
        }

        const int r0 = qbase + w * 16 + g;
        const int r1 = r0 + 8;
        float rm0 = -1e30f, rm1 = -1e30f;
        if (kt >= 2 * qt) {
            const int kb = kt * 32;
            #pragma unroll
            for (int ni = 0; ni < 4; ni++) {
                const int c0 = kb + ni * 8 + 2 * tg;
                float v0 = sacc[ni][0] * scale; if (c0     > r0) v0 = -1e30f;
                float v1 = sacc[ni][1] * scale; if (c0 + 1 > r0) v1 = -1e30f;
                float v2 = sacc[ni][2] * scale; if (c0     > r1) v2 = -1e30f;
                float v3 = sacc[ni][3] * scale; if (c0 + 1 > r1) v3 = -1e30f;
                sacc[ni][0] = v0; sacc[ni][1] = v1; sacc[ni][2] = v2; sacc[ni][3] = v3;
                rm0 = fmaxf(rm0, fmaxf(v0, v1));
                rm1 = fmaxf(rm1, fmaxf(v2, v3));
            }
        } else {
            #pragma unroll
            for (int ni = 0; ni < 4; ni++) {
                float v0 = sacc[ni][0] * scale;
                float v1 = sacc[ni][1] * scale;
                float v2 = sacc[ni][2] * scale;
                float v3 = sacc[ni][3] * scale;
                sacc[ni][0] = v0; sacc[ni][1] = v1; sacc[ni][2] = v2; sacc[ni][3] = v3;
                rm0 = fmaxf(rm0, fmaxf(v0, v1));
                rm1 = fmaxf(rm1, fmaxf(v2, v3));
            }
        }
        rm0 = fmaxf(rm0, __shfl_xor_sync(0xffffffffu, rm0, 1));
        rm0 = fmaxf(rm0, __shfl_xor_sync(0xffffffffu, rm0, 2));
        rm1 = fmaxf(rm1, __shfl_xor_sync(0xffffffffu, rm1, 1));
        rm1 = fmaxf(rm1, __shfl_xor_sync(0xffffffffu, rm1, 2));

        const float mn0 = fmaxf(m0, rm0);
        const float mn1 = fmaxf(m1, rm1);
        const float f0 = __expf(m0 - mn0);
        const float f1 = __expf(m1 - mn1);
        m0 = mn0; m1 = mn1;

        float ps0 = 0.0f, ps1 = 0.0f;
        #pragma unroll
        for (int ni = 0; ni < 4; ni++) {
            float p0 = __expf(sacc[ni][0] - mn0);
            float p1 = __expf(sacc[ni][1] - mn0);
            float p2 = __expf(sacc[ni][2] - mn1);
            float p3 = __expf(sacc[ni][3] - mn1);
            sacc[ni][0] = p0; sacc[ni][1] = p1; sacc[ni][2] = p2; sacc[ni][3] = p3;
            ps0 += p0 + p1;
            ps1 += p2 + p3;
        }
        ps0 += __shfl_xor_sync(0xffffffffu, ps0, 1);
        ps0 += __shfl_xor_sync(0xffffffffu, ps0, 2);
        ps1 += __shfl_xor_sync(0xffffffffu, ps1, 1);
        ps1 += __shfl_xor_sync(0xffffffffu, ps1, 2);
        l0 = l0 * f0 + ps0;
        l1 = l1 * f1 + ps1;

        #pragma unroll
        for (int ni = 0; ni < 16; ni++) {
            oacc[ni][0] *= f0; oacc[ni][1] *= f0;
            oacc[ni][2] *= f1; oacc[ni][3] *= f1;
        }

        const int pq = w * 16 + g;
        #pragma unroll
        for (int ni = 0; ni < 4; ni++) {
            *(float2*)&Ps[pq * LDPK + ni * 8 + 2 * tg]       = make_float2(sacc[ni][0], sacc[ni][1]);
            *(float2*)&Ps[(pq + 8) * LDPK + ni * 8 + 2 * tg] = make_float2(sacc[ni][2], sacc[ni][3]);
        }
        __syncwarp();   // P rows are warp-private

        // ---- O += P @ V ----
        const float4* Vb4 = (const float4*)(sm + A_VS_OFF + s * A_VS_STF);
        #pragma unroll
        for (int kg2 = 0; kg2 < 2; kg2++) {
            uint32_t ha[2][4];
            #pragma unroll
            for (int hh = 0; hh < 2; hh++) {
                const int ks2 = 2 * kg2 + hh;
                ha[hh][0] = f2tf(Ps[pq * LDPK + ks2 * 8 + tg]);
                ha[hh][1] = f2tf(Ps[(pq + 8) * LDPK + ks2 * 8 + tg]);
                ha[hh][2] = f2tf(Ps[pq * LDPK + ks2 * 8 + tg + 4]);
                ha[hh][3] = f2tf(Ps[(pq + 8) * LDPK + ks2 * 8 + tg + 4]);
            }
            const float4* Vrow = Vb4 + (kg2 * 4 + tg) * 130;
            #pragma unroll
            for (int ni = 0; ni < 16; ni++) {
                float4 vv = Vrow[ni * 8 + g];
                mma_tf32(oacc[ni], ha[0][0], ha[0][1], ha[0][2], ha[0][3], FU(vv.x), FU(vv.y));
                mma_tf32(oacc[ni], ha[1][0], ha[1][1], ha[1][2], ha[1][3], FU(vv.z), FU(vv.w));
            }
        }
    }

    // ---- epilogue: O / l -> g_attn fp32 ----
    const float il0 = 1.0f / l0;
    const float il1 = 1.0f / l1;
    const size_t row0 = rowbase + qbase + w * 16 + g;
    #pragma unroll
    for (int ni = 0; ni < 16; ni++) {
        const int col = hoff + ni * 8 + 2 * tg;
        *(float2*)&g_attn[row0 * DD + col] =
            make_float2(oacc[ni][0] * il0, oacc[ni][1] * il0);
        *(float2*)&g_attn[(row0 + 8) * DD + col] =
            make_float2(oacc[ni][2] * il1, oacc[ni][3] * il1);
    }
}

// ---------------- launch ----------------
extern "C" void kernel_launch(void* const* d_in, const int* in_sizes, int n_in,
                              void* d_out, int out_size)
{
    const float* x    = (const float*)d_in[0];
    const float* Wkqv = (const float*)d_in[1];
    const float* bkqv = (const float*)d_in[2];
    const float* Wo   = (const float*)d_in[3];
    const float* bo   = (const float*)d_in[4];
    float* out = (float*)d_out;

    float *kqv, *attn, *xp, *wkp, *wop, *ap, *ct, *st;
    cudaGetSymbolAddress((void**)&kqv, g_kqv);
    cudaGetSymbolAddress((void**)&attn, g_attn);
    cudaGetSymbolAddress((void**)&xp,  g_xp);
    cudaGetSymbolAddress((void**)&wkp, g_wkp);
    cudaGetSymbolAddress((void**)&wop, g_wop);
    cudaGetSymbolAddress((void**)&ap,  g_ap);
    cudaGetSymbolAddress((void**)&ct,  g_cos);
    cudaGetSymbolAddress((void**)&st,  g_sin);

    cudaFuncSetAttribute(gemm_packed_kernel, cudaFuncAttributeMaxDynamicSharedMemorySize, GEMM_SMEM);
    cudaFuncSetAttribute(attn_mma_kernel,    cudaFuncAttributeMaxDynamicSharedMemorySize, ATT_SMEM);

    // launch order arranged so launch #5 (0-based) = attn_mma for ncu capture (-s 5 -c 1)
    trig_kernel<<<(TT * 64) / 256, 256>>>(ct, st);                              // 0
    packA_kernel<<<dim3(DD / 64, MROWS / 32), 256>>>(x, (float4*)xp, MROWS, DD);// 1
    packB_kernel<<<(DD / 4 * N3 + 255) / 256, 256>>>(Wkqv, (float4*)wkp, DD, N3);// 2
    gemm_packed_kernel<<<dim3(N3 / 128, MROWS / 128), 256, GEMM_SMEM>>>(        // 3
        (const float4*)xp, (const float4*)wkp, bkqv, kqv, MROWS, N3, DD, 1, ct, st);
    pack_kv_kernel<<<dim3(TT / 32, BB * HH), 256>>>();                          // 4
    attn_mma_kernel<<<dim3(TT / 64, BB * HH), 128, ATT_SMEM>>>();               // 5 <- profiled
    packB_kernel<<<(DD / 4 * DD + 255) / 256, 256>>>(Wo, (float4*)wop, DD, DD); // 6
    packA_kernel<<<dim3(DD / 64, MROWS / 32), 256>>>(attn, (float4*)ap, MROWS, DD); // 7
    gemm_packed_kernel<<<dim3(DD / 128, MROWS / 128), 256, GEMM_SMEM>>>(        // 8
        (const float4*)ap, (const float4*)wop, bo, out, MROWS, DD, DD, 0, ct, st);
}

// round 13
// speedup vs baseline: 1.0145x; 1.0104x over previous
#include <cuda_runtime.h>
#include <math.h>
#include <stdint.h>

#define BB    2
#define TT    2048
#define DD    2048
#define HH    16
#define DK    128
#define N3    (3*DD)
#define MROWS (BB*TT)   // 4096

// ---------------- scratch (device globals; no allocation allowed) ----------------
__device__ float g_kqv[(size_t)MROWS * N3];    // q section used (k/v go packed)
__device__ float g_xp[(size_t)MROWS * DD];     // x packed (tf32)   [ck][M] float4 cells
__device__ float g_wkp[(size_t)DD * N3];       // Wkqv packed       [ck][N] float4 cells
__device__ float g_wop[(size_t)DD * DD];       // Wo packed
__device__ float g_ap[(size_t)MROWS * DD];     // attn out packed (written by attention)
__device__ float4 g_kp[(size_t)32 * 32 * TT];    // K frag-packed: [bh][ck d-cell][key]
__device__ float4 g_vp[(size_t)32 * 512 * 128];  // V frag-packed: [bh][ckv key-cell][d]
__device__ float g_cos[TT * 64];
__device__ float g_sin[TT * 64];

// ---------------- PTX helpers ----------------
__device__ __forceinline__ uint32_t smem_u32(const void* p) {
    return (uint32_t)__cvta_generic_to_shared(p);
}
__device__ __forceinline__ void cp16s(uint32_t dst, const void* src) {
    asm volatile("cp.async.cg.shared.global [%0], [%1], 16;\n" :: "r"(dst), "l"(src));
}
__device__ __forceinline__ void cp16(void* dst, const void* src) {
    asm volatile("cp.async.cg.shared.global [%0], [%1], 16;\n"
                 :: "r"(smem_u32(dst)), "l"(src));
}
__device__ __forceinline__ void cp_commit() {
    asm volatile("cp.async.commit_group;\n");
}
template<int N>
__device__ __forceinline__ void cp_wait() {
    asm volatile("cp.async.wait_group %0;\n" :: "n"(N));
}
__device__ __forceinline__ uint32_t f2tf(float f) {
    uint32_t r;
    asm("cvt.rna.tf32.f32 %0, %1;" : "=r"(r) : "f"(f));
    return r;
}
__device__ __forceinline__ float tfr(float f) {
    return __uint_as_float(f2tf(f));
}
__device__ __forceinline__ void mma_tf32(float c[4],
                                         uint32_t a0, uint32_t a1, uint32_t a2, uint32_t a3,
                                         uint32_t b0, uint32_t b1) {
    asm volatile(
        "mma.sync.aligned.m16n8k8.row.col.f32.tf32.tf32.f32 "
        "{%0,%1,%2,%3}, {%4,%5,%6,%7}, {%8,%9}, {%0,%1,%2,%3};\n"
        : "+f"(c[0]), "+f"(c[1]), "+f"(c[2]), "+f"(c[3])
        : "r"(a0), "r"(a1), "r"(a2), "r"(a3), "r"(b0), "r"(b1));
}
#define FU(x) __float_as_uint(x)

// ---------------- RoPE trig tables ----------------
__global__ void trig_kernel(float* __restrict__ ct, float* __restrict__ st)
{
    int idx = blockIdx.x * blockDim.x + threadIdx.x;
    if (idx >= TT * 64) return;
    int tpos = idx >> 6;
    int p    = idx & 63;
    float invf = (float)pow(10000.0, -(double)p / 64.0);
    float ang = (float)tpos * invf;
    float s, c;
    sincosf(ang, &s, &c);
    ct[idx] = c;
    st[idx] = s;
}

// ---------------- pack kernels (GEMM operands) ----------------
__global__ void packA_kernel(const float* __restrict__ in, float4* __restrict__ out,
                             int Mt, int K)
{
    __shared__ float tile[32][65];
    const int k0 = blockIdx.x * 64;
    const int m0 = blockIdx.y * 32;
    const int t  = threadIdx.x;
    #pragma unroll
    for (int i = 0; i < 2; i++) {
        int u = t + (i << 8);
        int m = u >> 4;
        int kc = u & 15;
        float4 v = *(const float4*)&in[(size_t)(m0 + m) * K + k0 + kc * 4];
        tile[m][kc * 4 + 0] = v.x;
        tile[m][kc * 4 + 1] = v.y;
        tile[m][kc * 4 + 2] = v.z;
        tile[m][kc * 4 + 3] = v.w;
    }
    __syncthreads();
    #pragma unroll
    for (int i = 0; i < 2; i++) {
        int u  = t + (i << 8);
        int ck = u >> 5;
        int m  = u & 31;
        int kg = ck >> 2, tg = ck & 3;
        int kb = kg * 16 + tg;
        float4 v;
        v.x = tfr(tile[m][kb]);
        v.y = tfr(tile[m][kb + 4]);
        v.z = tfr(tile[m][kb + 8]);
        v.w = tfr(tile[m][kb + 12]);
        out[(size_t)((k0 / 16 + kg) * 4 + tg) * Mt + m0 + m] = v;
    }
}

__global__ void packB_kernel(const float* __restrict__ W, float4* __restrict__ out,
                             int K, int N)
{
    int idx = blockIdx.x * 256 + threadIdx.x;
    int total = (K / 4) * N;
    if (idx >= total) return;
    int ck = idx / N;
    int n  = idx - ck * N;
    int kg = ck >> 2, tg = ck & 3;
    int kb = kg * 16 + tg;
    float4 v;
    v.x = tfr(W[(size_t)kb * N + n]);
    v.y = tfr(W[(size_t)(kb + 4) * N + n]);
    v.z = tfr(W[(size_t)(kb + 8) * N + n]);
    v.w = tfr(W[(size_t)(kb + 12) * N + n]);
    out[(size_t)ck * N + n] = v;
}

// ---------------- packed TF32 GEMM: CTA 128x128, warp 64x32, BK=32/stage, 3 stages ----------------
// mode 1 (QKV): col-block = one head-section. q -> g_kqv (rope); k -> g_kp packed (rope);
//               v -> g_vp packed. k/v pack via smem bounce in the dead stage buffers.
#define HALF_CELLS  1040                     // 8*130
#define STAGE_BYTES (2 * HALF_CELLS * 16)    // 33280
#define GEMM_SMEM   (3 * STAGE_BYTES)        // 99840  (>= 128*133*4 = 68096 for S bounce)
#define LDS_S 133

__global__ __launch_bounds__(256, 2)
void gemm_packed_kernel(const float4* __restrict__ Ap, const float4* __restrict__ Bp,
                        const float* __restrict__ bias, float* __restrict__ C,
                        int Mt, int Nt, int K, int mode,
                        const float* __restrict__ ct, const float* __restrict__ st)
{
    extern __shared__ char smx[];
    const uint32_t sb = smem_u32(smx);
    const int t    = threadIdx.x;
    const int wid  = t >> 5;
    const int lane = t & 31;
    const int g    = lane >> 2;
    const int tg   = lane & 3;
    const int wm   = wid & 1;
    const int wn   = wid >> 1;
    const int rowBase = blockIdx.y * 128;
    const int colBase = blockIdx.x * 128;

    float acc[4][4][4];
    #pragma unroll
    for (int mi = 0; mi < 4; mi++)
        #pragma unroll
        for (int ni = 0; ni < 4; ni++)
            #pragma unroll
            for (int r = 0; r < 4; r++) acc[mi][ni][r] = 0.0f;

    const int NK = K / 32;

    auto issue = [&](int kt) {
        const uint32_t base = sb + (kt % 3) * STAGE_BYTES;
        #pragma unroll
        for (int i = 0; i < 8; i++) {
            const int u = t + (i << 8);
            if (u < 1024) {
                const int tg8 = u >> 7, mm = u & 127;
                cp16s(base + (tg8 * 130 + mm) * 16,
                      Ap + ((size_t)(kt * 8 + tg8) * Mt + rowBase + mm));
            } else {
                const int v = u - 1024;
                const int tg8 = v >> 7, mm = v & 127;
                cp16s(base + (HALF_CELLS + tg8 * 130 + mm) * 16,
                      Bp + ((size_t)(kt * 8 + tg8) * Nt + colBase + mm));
            }
        }
        cp_commit();
    };

    issue(0);
    issue(1);

    for (int kt = 0; kt < NK; kt++) {
        cp_wait<1>();
        __syncthreads();
        if (kt + 2 < NK) issue(kt + 2);

        const float* Stg = (const float*)(smx + (kt % 3) * STAGE_BYTES);

        #pragma unroll
        for (int sub = 0; sub < 2; sub++) {
            const float* Asl = Stg + (sub * 4 + tg) * 130 * 4;
            const float* Bsl = Stg + (HALF_CELLS + (sub * 4 + tg) * 130) * 4;

            float4 A0[4], A1[4], Bv[4];
            #pragma unroll
            for (int mi = 0; mi < 4; mi++) {
                const int mr = wm * 64 + mi * 16 + g;
                A0[mi] = *(const float4*)&Asl[mr * 4];
                A1[mi] = *(const float4*)&Asl[(mr + 8) * 4];
            }
            #pragma unroll
            for (int ni = 0; ni < 4; ni++)
                Bv[ni] = *(const float4*)&Bsl[(wn * 32 + ni * 8 + g) * 4];

            #pragma unroll
            for (int mi = 0; mi < 4; mi++)
                #pragma unroll
                for (int ni = 0; ni < 4; ni++) {
                    mma_tf32(acc[mi][ni], FU(A0[mi].x), FU(A1[mi].x), FU(A0[mi].y), FU(A1[mi].y),
                             FU(Bv[ni].x), FU(Bv[ni].y));
                    mma_tf32(acc[mi][ni], FU(A0[mi].z), FU(A1[mi].z), FU(A0[mi].w), FU(A1[mi].w),
                             FU(Bv[ni].z), FU(Bv[ni].w));
                }
        }
    }
    cp_wait<0>();

    const int sect = (mode == 1) ? (colBase >> 11) : -1;

    if (mode == 0 || sect == 1) {
        // ---- plain epilogue: bias (+rope+tfr for q section), store to C ----
        #pragma unroll
        for (int mi = 0; mi < 4; mi++) {
            const int r0 = rowBase + wm * 64 + mi * 16 + g;
            const int r1 = r0 + 8;
            #pragma unroll
            for (int ni = 0; ni < 4; ni++) {
                const int c = colBase + wn * 32 + ni * 8 + tg * 2;
                const float2 b2 = *(const float2*)&bias[c];
                float v0 = acc[mi][ni][0] + b2.x;
                float v1 = acc[mi][ni][1] + b2.y;
                float v2 = acc[mi][ni][2] + b2.x;
                float v3 = acc[mi][ni][3] + b2.y;
                if (sect == 1) {
                    const int pj = (c & 127) >> 1;
                    const float c0 = ct[(r0 & (TT - 1)) * 64 + pj];
                    const float s0 = st[(r0 & (TT - 1)) * 64 + pj];
                    const float c1 = ct[(r1 & (TT - 1)) * 64 + pj];
                    const float s1 = st[(r1 & (TT - 1)) * 64 + pj];
                    float e0 = v0 * c0 - v1 * s0, o0 = v0 * s0 + v1 * c0;
                    float e1 = v2 * c1 - v3 * s1, o1 = v2 * s1 + v3 * c1;
                    v0 = tfr(e0); v1 = tfr(o0); v2 = tfr(e1); v3 = tfr(o1);
                }
                *(float2*)&C[(size_t)r0 * Nt + c] = make_float2(v0, v1);
                *(float2*)&C[(size_t)r1 * Nt + c] = make_float2(v2, v3);
            }
        }
    } else {
        // ---- k (sect 0, rope) / v (sect 2) : bounce via smem, store packed ----
        float* S = (float*)smx;   // [128][LDS_S], scalar access only
        __syncthreads();          // all warps out of mainloop smem reads
        #pragma unroll
        for (int mi = 0; mi < 4; mi++) {
            const int lr0 = wm * 64 + mi * 16 + g;
            const int lr1 = lr0 + 8;
            const int r0 = rowBase + lr0;
            const int r1 = rowBase + lr1;
            #pragma unroll
            for (int ni = 0; ni < 4; ni++) {
                const int lc = wn * 32 + ni * 8 + tg * 2;
                const int c  = colBase + lc;
                const float2 b2 = *(const float2*)&bias[c];
                float v0 = acc[mi][ni][0] + b2.x;
                float v1 = acc[mi][ni][1] + b2.y;
                float v2 = acc[mi][ni][2] + b2.x;
                float v3 = acc[mi][ni][3] + b2.y;
                if (sect == 0) {
                    const int pj = (c & 127) >> 1;
                    const float c0 = ct[(r0 & (TT - 1)) * 64 + pj];
                    const float s0 = st[(r0 & (TT - 1)) * 64 + pj];
                    const float c1 = ct[(r1 & (TT - 1)) * 64 + pj];
                    const float s1 = st[(r1 & (TT - 1)) * 64 + pj];
                    float e0 = v0 * c0 - v1 * s0, o0 = v0 * s0 + v1 * c0;
                    float e1 = v2 * c1 - v3 * s1, o1 = v2 * s1 + v3 * c1;
                    v0 = e0; v1 = o0; v2 = e1; v3 = o1;
                }
                S[lr0 * LDS_S + lc]     = tfr(v0);
                S[lr0 * LDS_S + lc + 1] = tfr(v1);
                S[lr1 * LDS_S + lc]     = tfr(v2);
                S[lr1 * LDS_S + lc + 1] = tfr(v3);
            }
        }
        __syncthreads();

        const int head = (colBase & 2047) >> 7;
        const int bh   = (rowBase >> 11) * 16 + head;
        const int keybase = rowBase & 2047;
        if (sect == 0) {
            // K cells: 32 ck x 128 keys
            #pragma unroll
            for (int i = 0; i < 16; i++) {
                int idx = t + (i << 8);
                int ck  = idx >> 7;
                int key = idx & 127;
                int kb  = (ck >> 2) * 16 + (ck & 3);
                float4 o = make_float4(S[key * LDS_S + kb],     S[key * LDS_S + kb + 4],
                                       S[key * LDS_S + kb + 8], S[key * LDS_S + kb + 12]);
                g_kp[((size_t)bh * 32 + ck) * TT + keybase + key] = o;
            }
        } else {
            // V cells: 32 local ckv x 128 d
            #pragma unroll
            for (int i = 0; i < 16; i++) {
                int idx = t + (i << 8);
                int cl  = idx >> 7;            // 0..31
                int d   = idx & 127;
                int kgl = cl >> 2, tgv = cl & 3;
                int kbv = kgl * 16 + tgv;
                float4 o = make_float4(S[kbv * LDS_S + d],        S[(kbv + 4) * LDS_S + d],
                                       S[(kbv + 8) * LDS_S + d],  S[(kbv + 12) * LDS_S + d]);
                int ckvG = (keybase / 16 + kgl) * 4 + tgv;
                g_vp[((size_t)bh * 512 + ckvG) * 128 + d] = o;
            }
        }
    }
}

// ---------------- Flash attention: 64q CTAs, 128 thr, 32-key tiles, 2 CTAs/SM ----------------
#define A_KS_STF (32 * 34 * 4)               // 4352 floats/stage
#define A_VS_STF (8 * 130 * 4)               // 4160 floats/stage
#define A_VS_OFF (2 * A_KS_STF)              // 8704
#define A_PS_OFF (A_VS_OFF + 2 * A_VS_STF)   // 17024
#define LDPK 132                             // 16B-aligned rows (float4/float2 access!)
#define ATT_SMEM ((A_PS_OFF + 64 * LDPK) * 4)   // 101888 B -> 2 CTAs/SM

__global__ __launch_bounds__(128, 2)
void attn_mma_kernel()
{
    extern __shared__ float sm[];
    float* Ps = sm + A_PS_OFF;

    const int t    = threadIdx.x;
    const int lane = t & 31;
    const int w    = t >> 5;
    const int g    = lane >> 2;
    const int tg   = lane & 3;
    const int bh = blockIdx.y;
    const int b  = bh >> 4;
    const int h  = bh & 15;
    const int qt = (int)gridDim.x - 1 - (int)blockIdx.x;
    const int qbase = qt * 64;
    const size_t rowbase = (size_t)b * TT;
    const int hoff = h * DK;
    const float scale = 0.08838834764831845f;

    for (int u = t; u < 64 * 32; u += 128) {
        int qi = u >> 5;
        int c  = u & 31;
        float4 v = *(const float4*)&g_kqv[(rowbase + qbase + qi) * N3 + DD + hoff + c * 4];
        *(float4*)&Ps[qi * LDPK + c * 4] = v;
    }
    __syncthreads();
    const int qr = w * 16 + g;
    uint32_t qf[16][4];
    #pragma unroll
    for (int ks = 0; ks < 16; ks++) {
        qf[ks][0] = *(const uint32_t*)&Ps[qr * LDPK + ks * 8 + tg];
        qf[ks][1] = *(const uint32_t*)&Ps[(qr + 8) * LDPK + ks * 8 + tg];
        qf[ks][2] = *(const uint32_t*)&Ps[qr * LDPK + ks * 8 + tg + 4];
        qf[ks][3] = *(const uint32_t*)&Ps[(qr + 8) * LDPK + ks * 8 + tg + 4];
    }
    __syncthreads();

    float oacc[16][4];
    #pragma unroll
    for (int ni = 0; ni < 16; ni++)
        #pragma unroll
        for (int r = 0; r < 4; r++) oacc[ni][r] = 0.0f;
    float m0 = -1e30f, m1 = -1e30f, l0 = 0.0f, l1 = 0.0f;

    auto issue_tile = [&](int kt) {
        const int s = kt & 1;
        float* Kst = sm + s * A_KS_STF;
        float* Vst = sm + A_VS_OFF + s * A_VS_STF;
        #pragma unroll
        for (int i = 0; i < 8; i++) {
            int u = t + (i << 7);
            int r = u >> 5;
            int c = u & 31;
            cp16(Kst + (r * 34 + c) * 4,
                 g_kp + ((size_t)bh * 32 + r) * TT + kt * 32 + c);
        }
        #pragma unroll
        for (int i = 0; i < 8; i++) {
            int u = t + (i << 7);
            int r = u >> 7;
            int c = u & 127;
            cp16(Vst + (r * 130 + c) * 4,
                 g_vp + ((size_t)bh * 512 + kt * 8 + r) * 128 + c);
        }
        cp_commit();
    };

    const int nkt = 2 * qt + 2;
    issue_tile(0);

    for (int kt = 0; kt < nkt; kt++) {
        const int s = kt & 1;
        __syncthreads();
        if (kt + 1 < nkt) issue_tile(kt + 1);
        cp_wait<1>();
        __syncthreads();

        float sacc[4][4];
        #pragma unroll
        for (int ni = 0; ni < 4; ni++)
            #pragma unroll
            for (int r = 0; r < 4; r++) sacc[ni][r] = 0.0f;

        const float4* Kb4 = (const float4*)(sm + s * A_KS_STF);
        #pragma unroll
        for (int kg = 0; kg < 8; kg++) {
            const float4* Krow = Kb4 + (kg * 4 + tg) * 34;
            #pragma unroll
            for (int ni = 0; ni < 4; ni++) {
                float4 bv = Krow[ni * 8 + g];
                mma_tf32(sacc[ni], qf[2 * kg][0], qf[2 * kg][1], qf[2 * kg][2], qf[2 * kg][3],
                         FU(bv.x), FU(bv.y));
                mma_tf32(sacc[ni], qf[2 * kg + 1][0], qf[2 * kg + 1][1], qf[2 * kg + 1][2], qf[2 * kg + 1][3],
                         FU(bv.z), FU(bv.w));
            }
        }

        const int r0 = qbase + w * 16 + g;
        const int r1 = r0 + 8;
        float rm0 = -1e30f, rm1 = -1e30f;
        if (kt >= 2 * qt) {
            const int kb = kt * 32;
            #pragma unroll
            for (int ni = 0; ni < 4; ni++) {
                const int c0 = kb + ni * 8 + 2 * tg;
                float v0 = sacc[ni][0] * scale; if (c0     > r0) v0 = -1e30f;
                float v1 = sacc[ni][1] * scale; if (c0 + 1 > r0) v1 = -1e30f;
                float v2 = sacc[ni][2] * scale; if (c0     > r1) v2 = -1e30f;
                float v3 = sacc[ni][3] * scale; if (c0 + 1 > r1) v3 = -1e30f;
                sacc[ni][0] = v0; sacc[ni][1] = v1; sacc[ni][2] = v2; sacc[ni][3] = v3;
                rm0 = fmaxf(rm0, fmaxf(v0, v1));
                rm1 = fmaxf(rm1, fmaxf(v2, v3));
            }
        } else {
            #pragma unroll
            for (int ni = 0; ni < 4; ni++) {
                float v0 = sacc[ni][0] * scale;
                float v1 = sacc[ni][1] * scale;
                float v2 = sacc[ni][2] * scale;
                float v3 = sacc[ni][3] * scale;
                sacc[ni][0] = v0; sacc[ni][1] = v1; sacc[ni][2] = v2; sacc[ni][3] = v3;
                rm0 = fmaxf(rm0, fmaxf(v0, v1));
                rm1 = fmaxf(rm1, fmaxf(v2, v3));
            }
        }
        rm0 = fmaxf(rm0, __shfl_xor_sync(0xffffffffu, rm0, 1));
        rm0 = fmaxf(rm0, __shfl_xor_sync(0xffffffffu, rm0, 2));
        rm1 = fmaxf(rm1, __shfl_xor_sync(0xffffffffu, rm1, 1));
        rm1 = fmaxf(rm1, __shfl_xor_sync(0xffffffffu, rm1, 2));

        const float mn0 = fmaxf(m0, rm0);
        const float mn1 = fmaxf(m1, rm1);
        const float f0 = __expf(m0 - mn0);
        const float f1 = __expf(m1 - mn1);
        m0 = mn0; m1 = mn1;

        float ps0 = 0.0f, ps1 = 0.0f;
        #pragma unroll
        for (int ni = 0; ni < 4; ni++) {
            float p0 = __expf(sacc[ni][0] - mn0);
            float p1 = __expf(sacc[ni][1] - mn0);
            float p2 = __expf(sacc[ni][2] - mn1);
            float p3 = __expf(sacc[ni][3] - mn1);
            sacc[ni][0] = p0; sacc[ni][1] = p1; sacc[ni][2] = p2; sacc[ni][3] = p3;
            ps0 += p0 + p1;
            ps1 += p2 + p3;
        }
        ps0 += __shfl_xor_sync(0xffffffffu, ps0, 1);
        ps0 += __shfl_xor_sync(0xffffffffu, ps0, 2);
        ps1 += __shfl_xor_sync(0xffffffffu, ps1, 1);
        ps1 += __shfl_xor_sync(0xffffffffu, ps1, 2);
        l0 = l0 * f0 + ps0;
        l1 = l1 * f1 + ps1;

        #pragma unroll
        for (int ni = 0; ni < 16; ni++) {
            oacc[ni][0] *= f0; oacc[ni][1] *= f0;
            oacc[ni][2] *= f1; oacc[ni][3] *= f1;
        }

        const int pq = w * 16 + g;
        #pragma unroll
        for (int ni = 0; ni < 4; ni++) {
            *(float2*)&Ps[pq * LDPK + ni * 8 + 2 * tg]       = make_float2(sacc[ni][0], sacc[ni][1]);
            *(float2*)&Ps[(pq + 8) * LDPK + ni * 8 + 2 * tg] = make_float2(sacc[ni][2], sacc[ni][3]);
        }
        __syncwarp();

        const float4* Vb4 = (const float4*)(sm + A_VS_OFF + s * A_VS_STF);
        #pragma unroll
        for (int kg2 = 0; kg2 < 2; kg2++) {
            uint32_t ha[2][4];
            #pragma unroll
            for (int hh = 0; hh < 2; hh++) {
                const int ks2 = 2 * kg2 + hh;
                ha[hh][0] = f2tf(Ps[pq * LDPK + ks2 * 8 + tg]);
                ha[hh][1] = f2tf(Ps[(pq + 8) * LDPK + ks2 * 8 + tg]);
                ha[hh][2] = f2tf(Ps[pq * LDPK + ks2 * 8 + tg + 4]);
                ha[hh][3] = f2tf(Ps[(pq + 8) * LDPK + ks2 * 8 + tg + 4]);
            }
            const float4* Vrow = Vb4 + (kg2 * 4 + tg) * 130;
            #pragma unroll
            for (int ni = 0; ni < 16; ni++) {
                float4 vv = Vrow[ni * 8 + g];
                mma_tf32(oacc[ni], ha[0][0], ha[0][1], ha[0][2], ha[0][3], FU(vv.x), FU(vv.y));
                mma_tf32(oacc[ni], ha[1][0], ha[1][1], ha[1][2], ha[1][3], FU(vv.z), FU(vv.w));
            }
        }
    }

    // ---- epilogue: O/l -> Ps (tf32-rounded) -> g_ap packed ----
    const float il0 = 1.0f / l0;
    const float il1 = 1.0f / l1;
    const int lr0 = w * 16 + g;
    const int lr1 = lr0 + 8;
    __syncthreads();
    #pragma unroll
    for (int ni = 0; ni < 16; ni++) {
        const int lc = ni * 8 + 2 * tg;
        Ps[lr0 * LDPK + lc]     = tfr(oacc[ni][0] * il0);
        Ps[lr0 * LDPK + lc + 1] = tfr(oacc[ni][1] * il0);
        Ps[lr1 * LDPK + lc]     = tfr(oacc[ni][2] * il1);
        Ps[lr1 * LDPK + lc + 1] = tfr(oacc[ni][3] * il1);
    }
    __syncthreads();

    float4* ap4 = (float4*)g_ap;
    const size_t mrow0 = rowbase + qbase;
    #pragma unroll
    for (int i = 0; i < 16; i++) {
        int idx = t + (i << 7);       // 2048 cells = 32 ck x 64 m
        int ck  = idx >> 6;
        int m   = idx & 63;
        int kb  = (ck >> 2) * 16 + (ck & 3);
        float4 o = make_float4(Ps[m * LDPK + kb],     Ps[m * LDPK + kb + 4],
                               Ps[m * LDPK + kb + 8], Ps[m * LDPK + kb + 12]);
        ap4[(size_t)(32 * h + ck) * MROWS + mrow0 + m] = o;
    }
}

// ---------------- launch ----------------
extern "C" void kernel_launch(void* const* d_in, const int* in_sizes, int n_in,
                              void* d_out, int out_size)
{
    const float* x    = (const float*)d_in[0];
    const float* Wkqv = (const float*)d_in[1];
    const float* bkqv = (const float*)d_in[2];
    const float* Wo   = (const float*)d_in[3];
    const float* bo   = (const float*)d_in[4];
    float* out = (float*)d_out;

    float *kqv, *xp, *wkp, *wop, *ap, *ct, *st;
    cudaGetSymbolAddress((void**)&kqv, g_kqv);
    cudaGetSymbolAddress((void**)&xp,  g_xp);
    cudaGetSymbolAddress((void**)&wkp, g_wkp);
    cudaGetSymbolAddress((void**)&wop, g_wop);
    cudaGetSymbolAddress((void**)&ap,  g_ap);
    cudaGetSymbolAddress((void**)&ct,  g_cos);
    cudaGetSymbolAddress((void**)&st,  g_sin);

    cudaFuncSetAttribute(gemm_packed_kernel, cudaFuncAttributeMaxDynamicSharedMemorySize, GEMM_SMEM);
    cudaFuncSetAttribute(attn_mma_kernel,    cudaFuncAttributeMaxDynamicSharedMemorySize, ATT_SMEM);

    // launch order: attn at index 5 for ncu capture (-s 5 -c 1)
    trig_kernel<<<(TT * 64) / 256, 256>>>(ct, st);                               // 0
    packA_kernel<<<dim3(DD / 64, MROWS / 32), 256>>>(x, (float4*)xp, MROWS, DD); // 1
    packB_kernel<<<(DD / 4 * N3 + 255) / 256, 256>>>(Wkqv, (float4*)wkp, DD, N3);// 2
    gemm_packed_kernel<<<dim3(N3 / 128, MROWS / 128), 256, GEMM_SMEM>>>(         // 3
        (const float4*)xp, (const float4*)wkp, bkqv, kqv, MROWS, N3, DD, 1, ct, st);
    packB_kernel<<<(DD / 4 * DD + 255) / 256, 256>>>(Wo, (float4*)wop, DD, DD);  // 4
    attn_mma_kernel<<<dim3(TT / 64, BB * HH), 128, ATT_SMEM>>>();                // 5 <- profiled
    gemm_packed_kernel<<<dim3(DD / 128, MROWS / 128), 256, GEMM_SMEM>>>(         // 6
        (const float4*)ap, (const float4*)wop, bo, out, MROWS, DD, DD, 0, ct, st);
}

// round 14
// speedup vs baseline: 1.0345x; 1.0198x over previous
#include <cuda_runtime.h>
#include <math.h>
#include <stdint.h>

#define BB    2
#define TT    2048
#define DD    2048
#define HH    16
#define DK    128
#define N3    (3*DD)
#define MROWS (BB*TT)   // 4096

// ---------------- scratch (device globals; no allocation allowed) ----------------
__device__ float g_kqv[(size_t)MROWS * N3];    // q section used (k/v go packed)
__device__ float g_xp[(size_t)MROWS * DD];     // x packed (tf32)   [ck][M] float4 cells
__device__ float g_wkp[(size_t)DD * N3];       // Wkqv packed       [ck][N] float4 cells
__device__ float g_wop[(size_t)DD * DD];       // Wo packed
__device__ float g_ap[(size_t)MROWS * DD];     // attn out packed (written by attention)
__device__ float4 g_kp[(size_t)32 * 32 * TT];    // K frag-packed: [bh][ck d-cell][key]
__device__ float4 g_vp[(size_t)32 * 512 * 128];  // V frag-packed: [bh][ckv key-cell][d]
__device__ float g_cos[TT * 64];
__device__ float g_sin[TT * 64];

// ---------------- PTX helpers ----------------
__device__ __forceinline__ uint32_t smem_u32(const void* p) {
    return (uint32_t)__cvta_generic_to_shared(p);
}
__device__ __forceinline__ void cp16s(uint32_t dst, const void* src) {
    asm volatile("cp.async.cg.shared.global [%0], [%1], 16;\n" :: "r"(dst), "l"(src));
}
__device__ __forceinline__ void cp_commit() {
    asm volatile("cp.async.commit_group;\n");
}
template<int N>
__device__ __forceinline__ void cp_wait() {
    asm volatile("cp.async.wait_group %0;\n" :: "n"(N));
}
__device__ __forceinline__ uint32_t f2tf(float f) {
    uint32_t r;
    asm("cvt.rna.tf32.f32 %0, %1;" : "=r"(r) : "f"(f));
    return r;
}
__device__ __forceinline__ float tfr(float f) {
    return __uint_as_float(f2tf(f));
}
__device__ __forceinline__ void mma_tf32(float c[4],
                                         uint32_t a0, uint32_t a1, uint32_t a2, uint32_t a3,
                                         uint32_t b0, uint32_t b1) {
    asm volatile(
        "mma.sync.aligned.m16n8k8.row.col.f32.tf32.tf32.f32 "
        "{%0,%1,%2,%3}, {%4,%5,%6,%7}, {%8,%9}, {%0,%1,%2,%3};\n"
        : "+f"(c[0]), "+f"(c[1]), "+f"(c[2]), "+f"(c[3])
        : "r"(a0), "r"(a1), "r"(a2), "r"(a3), "r"(b0), "r"(b1));
}
#define FU(x) __float_as_uint(x)

// ---------------- RoPE trig tables ----------------
__global__ void trig_kernel(float* __restrict__ ct, float* __restrict__ st)
{
    int idx = blockIdx.x * blockDim.x + threadIdx.x;
    if (idx >= TT * 64) return;
    int tpos = idx >> 6;
    int p    = idx & 63;
    float invf = (float)pow(10000.0, -(double)p / 64.0);
    float ang = (float)tpos * invf;
    float s, c;
    sincosf(ang, &s, &c);
    ct[idx] = c;
    st[idx] = s;
}

// ---------------- pack kernels (GEMM operands) ----------------
__global__ void packA_kernel(const float* __restrict__ in, float4* __restrict__ out,
                             int Mt, int K)
{
    __shared__ float tile[32][65];
    const int k0 = blockIdx.x * 64;
    const int m0 = blockIdx.y * 32;
    const int t  = threadIdx.x;
    #pragma unroll
    for (int i = 0; i < 2; i++) {
        int u = t + (i << 8);
        int m = u >> 4;
        int kc = u & 15;
        float4 v = *(const float4*)&in[(size_t)(m0 + m) * K + k0 + kc * 4];
        tile[m][kc * 4 + 0] = v.x;
        tile[m][kc * 4 + 1] = v.y;
        tile[m][kc * 4 + 2] = v.z;
        tile[m][kc * 4 + 3] = v.w;
    }
    __syncthreads();
    #pragma unroll
    for (int i = 0; i < 2; i++) {
        int u  = t + (i << 8);
        int ck = u >> 5;
        int m  = u & 31;
        int kg = ck >> 2, tg = ck & 3;
        int kb = kg * 16 + tg;
        float4 v;
        v.x = tfr(tile[m][kb]);
        v.y = tfr(tile[m][kb + 4]);
        v.z = tfr(tile[m][kb + 8]);
        v.w = tfr(tile[m][kb + 12]);
        out[(size_t)((k0 / 16 + kg) * 4 + tg) * Mt + m0 + m] = v;
    }
}

__global__ void packB_kernel(const float* __restrict__ W, float4* __restrict__ out,
                             int K, int N)
{
    int idx = blockIdx.x * 256 + threadIdx.x;
    int total = (K / 4) * N;
    if (idx >= total) return;
    int ck = idx / N;
    int n  = idx - ck * N;
    int kg = ck >> 2, tg = ck & 3;
    int kb = kg * 16 + tg;
    float4 v;
    v.x = tfr(W[(size_t)kb * N + n]);
    v.y = tfr(W[(size_t)(kb + 4) * N + n]);
    v.z = tfr(W[(size_t)(kb + 8) * N + n]);
    v.w = tfr(W[(size_t)(kb + 12) * N + n]);
    out[(size_t)ck * N + n] = v;
}

// ---------------- packed TF32 GEMM: CTA 128x128, warp 64x32, BK=32/stage, 3 stages ----------------
#define HALF_CELLS  1040                     // 8*130
#define STAGE_BYTES (2 * HALF_CELLS * 16)    // 33280
#define GEMM_SMEM   (3 * STAGE_BYTES)        // 99840  (>= 128*133*4 for S bounce)
#define LDS_S 133

__global__ __launch_bounds__(256, 2)
void gemm_packed_kernel(const float4* __restrict__ Ap, const float4* __restrict__ Bp,
                        const float* __restrict__ bias, float* __restrict__ C,
                        int Mt, int Nt, int K, int mode,
                        const float* __restrict__ ct, const float* __restrict__ st)
{
    extern __shared__ char smx[];
    const uint32_t sb = smem_u32(smx);
    const int t    = threadIdx.x;
    const int wid  = t >> 5;
    const int lane = t & 31;
    const int g    = lane >> 2;
    const int tg   = lane & 3;
    const int wm   = wid & 1;
    const int wn   = wid >> 1;
    const int rowBase = blockIdx.y * 128;
    const int colBase = blockIdx.x * 128;

    float acc[4][4][4];
    #pragma unroll
    for (int mi = 0; mi < 4; mi++)
        #pragma unroll
        for (int ni = 0; ni < 4; ni++)
            #pragma unroll
            for (int r = 0; r < 4; r++) acc[mi][ni][r] = 0.0f;

    const int NK = K / 32;

    // ---- incremental-pointer loader ----
    // u = t + 256*i  ->  tg8 = (t>>7) + 2*i,  mm = t&127 (i-invariant)
    const float4* srcA = Ap + (size_t)(t >> 7) * Mt + rowBase + (t & 127);
    const float4* srcB = Bp + (size_t)(t >> 7) * Nt + colBase + (t & 127);
    const uint32_t dstA0 = sb + (((t >> 7) * 130 + (t & 127)) << 4);
    const uint32_t dstB0 = dstA0 + HALF_CELLS * 16;
    uint32_t soff = 0;

    auto issue = [&]() {
        #pragma unroll
        for (int i = 0; i < 4; i++) {
            cp16s(dstA0 + soff + i * (2 * 130 * 16), srcA + (size_t)(2 * i) * Mt);
            cp16s(dstB0 + soff + i * (2 * 130 * 16), srcB + (size_t)(2 * i) * Nt);
        }
        cp_commit();
        srcA += (size_t)8 * Mt;
        srcB += (size_t)8 * Nt;
        soff = (soff == 2 * STAGE_BYTES) ? 0 : soff + STAGE_BYTES;
    };

    issue();
    issue();

    uint32_t stgoff = 0;
    for (int kt = 0; kt < NK; kt++) {
        cp_wait<1>();
        __syncthreads();
        if (kt + 2 < NK) issue();

        const float* Stg = (const float*)(smx + stgoff);
        stgoff = (stgoff == 2 * STAGE_BYTES) ? 0 : stgoff + STAGE_BYTES;

        #pragma unroll
        for (int sub = 0; sub < 2; sub++) {
            const float* Asl = Stg + (sub * 4 + tg) * 130 * 4;
            const float* Bsl = Stg + (HALF_CELLS + (sub * 4 + tg) * 130) * 4;

            float4 A0[4], A1[4], Bv[4];
            #pragma unroll
            for (int mi = 0; mi < 4; mi++) {
                const int mr = wm * 64 + mi * 16 + g;
                A0[mi] = *(const float4*)&Asl[mr * 4];
                A1[mi] = *(const float4*)&Asl[(mr + 8) * 4];
            }
            #pragma unroll
            for (int ni = 0; ni < 4; ni++)
                Bv[ni] = *(const float4*)&Bsl[(wn * 32 + ni * 8 + g) * 4];

            #pragma unroll
            for (int mi = 0; mi < 4; mi++)
                #pragma unroll
                for (int ni = 0; ni < 4; ni++) {
                    mma_tf32(acc[mi][ni], FU(A0[mi].x), FU(A1[mi].x), FU(A0[mi].y), FU(A1[mi].y),
                             FU(Bv[ni].x), FU(Bv[ni].y));
                    mma_tf32(acc[mi][ni], FU(A0[mi].z), FU(A1[mi].z), FU(A0[mi].w), FU(A1[mi].w),
                             FU(Bv[ni].z), FU(Bv[ni].w));
                }
        }
    }
    cp_wait<0>();

    const int sect = (mode == 1) ? (colBase >> 11) : -1;

    if (mode == 0 || sect == 1) {
        // ---- plain epilogue: bias (+rope+tfr for q section), store to C ----
        #pragma unroll
        for (int mi = 0; mi < 4; mi++) {
            const int r0 = rowBase + wm * 64 + mi * 16 + g;
            const int r1 = r0 + 8;
            #pragma unroll
            for (int ni = 0; ni < 4; ni++) {
                const int c = colBase + wn * 32 + ni * 8 + tg * 2;
                const float2 b2 = *(const float2*)&bias[c];
                float v0 = acc[mi][ni][0] + b2.x;
                float v1 = acc[mi][ni][1] + b2.y;
                float v2 = acc[mi][ni][2] + b2.x;
                float v3 = acc[mi][ni][3] + b2.y;
                if (sect == 1) {
                    const int pj = (c & 127) >> 1;
                    const float c0 = ct[(r0 & (TT - 1)) * 64 + pj];
                    const float s0 = st[(r0 & (TT - 1)) * 64 + pj];
                    const float c1 = ct[(r1 & (TT - 1)) * 64 + pj];
                    const float s1 = st[(r1 & (TT - 1)) * 64 + pj];
                    float e0 = v0 * c0 - v1 * s0, o0 = v0 * s0 + v1 * c0;
                    float e1 = v2 * c1 - v3 * s1, o1 = v2 * s1 + v3 * c1;
                    v0 = tfr(e0); v1 = tfr(o0); v2 = tfr(e1); v3 = tfr(o1);
                }
                *(float2*)&C[(size_t)r0 * Nt + c] = make_float2(v0, v1);
                *(float2*)&C[(size_t)r1 * Nt + c] = make_float2(v2, v3);
            }
        }
    } else {
        // ---- k (sect 0, rope) / v (sect 2) : bounce via smem, store packed ----
        float* S = (float*)smx;   // [128][LDS_S], scalar access only
        __syncthreads();
        #pragma unroll
        for (int mi = 0; mi < 4; mi++) {
            const int lr0 = wm * 64 + mi * 16 + g;
            const int lr1 = lr0 + 8;
            const int r0 = rowBase + lr0;
            const int r1 = rowBase + lr1;
            #pragma unroll
            for (int ni = 0; ni < 4; ni++) {
                const int lc = wn * 32 + ni * 8 + tg * 2;
                const int c  = colBase + lc;
                const float2 b2 = *(const float2*)&bias[c];
                float v0 = acc[mi][ni][0] + b2.x;
                float v1 = acc[mi][ni][1] + b2.y;
                float v2 = acc[mi][ni][2] + b2.x;
                float v3 = acc[mi][ni][3] + b2.y;
                if (sect == 0) {
                    const int pj = (c & 127) >> 1;
                    const float c0 = ct[(r0 & (TT - 1)) * 64 + pj];
                    const float s0 = st[(r0 & (TT - 1)) * 64 + pj];
                    const float c1 = ct[(r1 & (TT - 1)) * 64 + pj];
                    const float s1 = st[(r1 & (TT - 1)) * 64 + pj];
                    float e0 = v0 * c0 - v1 * s0, o0 = v0 * s0 + v1 * c0;
                    float e1 = v2 * c1 - v3 * s1, o1 = v2 * s1 + v3 * c1;
                    v0 = e0; v1 = o0; v2 = e1; v3 = o1;
                }
                S[lr0 * LDS_S + lc]     = tfr(v0);
                S[lr0 * LDS_S + lc + 1] = tfr(v1);
                S[lr1 * LDS_S + lc]     = tfr(v2);
                S[lr1 * LDS_S + lc + 1] = tfr(v3);
            }
        }
        __syncthreads();

        const int head = (colBase & 2047) >> 7;
        const int bh   = (rowBase >> 11) * 16 + head;
        const int keybase = rowBase & 2047;
        if (sect == 0) {
            #pragma unroll
            for (int i = 0; i < 16; i++) {
                int idx = t + (i << 8);
                int ck  = idx >> 7;
                int key = idx & 127;
                int kb  = (ck >> 2) * 16 + (ck & 3);
                float4 o = make_float4(S[key * LDS_S + kb],     S[key * LDS_S + kb + 4],
                                       S[key * LDS_S + kb + 8], S[key * LDS_S + kb + 12]);
                g_kp[((size_t)bh * 32 + ck) * TT + keybase + key] = o;
            }
        } else {
            #pragma unroll
            for (int i = 0; i < 16; i++) {
                int idx = t + (i << 8);
                int cl  = idx >> 7;
                int d   = idx & 127;
                int kgl = cl >> 2, tgv = cl & 3;
                int kbv = kgl * 16 + tgv;
                float4 o = make_float4(S[kbv * LDS_S + d],        S[(kbv + 4) * LDS_S + d],
                                       S[(kbv + 8) * LDS_S + d],  S[(kbv + 12) * LDS_S + d]);
                int ckvG = (keybase / 16 + kgl) * 4 + tgv;
                g_vp[((size_t)bh * 512 + ckvG) * 128 + d] = o;
            }
        }
    }
}

// ---------------- Flash attention: 64q CTAs, 128 thr, 32-key tiles, 2 CTAs/SM ----------------
#define A_KS_STF (32 * 34 * 4)               // 4352 floats/stage
#define A_VS_STF (8 * 130 * 4)               // 4160 floats/stage
#define A_VS_OFF (2 * A_KS_STF)              // 8704
#define A_PS_OFF (A_VS_OFF + 2 * A_VS_STF)   // 17024
#define LDPK 132                             // 16B-aligned rows
#define ATT_SMEM ((A_PS_OFF + 64 * LDPK) * 4)   // 101888 B -> 2 CTAs/SM

__global__ __launch_bounds__(128, 2)
void attn_mma_kernel()
{
    extern __shared__ float sm[];
    float* Ps = sm + A_PS_OFF;

    const int t    = threadIdx.x;
    const int lane = t & 31;
    const int w    = t >> 5;
    const int g    = lane >> 2;
    const int tg   = lane & 3;
    const int bh = blockIdx.y;
    const int b  = bh >> 4;
    const int h  = bh & 15;
    const int qt = (int)gridDim.x - 1 - (int)blockIdx.x;
    const int qbase = qt * 64;
    const size_t rowbase = (size_t)b * TT;
    const int hoff = h * DK;
    const float scale = 0.08838834764831845f;

    for (int u = t; u < 64 * 32; u += 128) {
        int qi = u >> 5;
        int c  = u & 31;
        float4 v = *(const float4*)&g_kqv[(rowbase + qbase + qi) * N3 + DD + hoff + c * 4];
        *(float4*)&Ps[qi * LDPK + c * 4] = v;
    }
    __syncthreads();
    const int qr = w * 16 + g;
    uint32_t qf[16][4];
    #pragma unroll
    for (int ks = 0; ks < 16; ks++) {
        qf[ks][0] = *(const uint32_t*)&Ps[qr * LDPK + ks * 8 + tg];
        qf[ks][1] = *(const uint32_t*)&Ps[(qr + 8) * LDPK + ks * 8 + tg];
        qf[ks][2] = *(const uint32_t*)&Ps[qr * LDPK + ks * 8 + tg + 4];
        qf[ks][3] = *(const uint32_t*)&Ps[(qr + 8) * LDPK + ks * 8 + tg + 4];
    }
    __syncthreads();

    float oacc[16][4];
    #pragma unroll
    for (int ni = 0; ni < 16; ni++)
        #pragma unroll
        for (int r = 0; r < 4; r++) oacc[ni][r] = 0.0f;
    float m0 = -1e30f, m1 = -1e30f, l0 = 0.0f, l1 = 0.0f;

    // ---- incremental-pointer tile loader ----
    // K: u = t + 128*i -> r = (t>>5)+4i, c = t&31 ; V: r = (t>>7)+i, c = t&127
    const float4* srcK = g_kp + (size_t)bh * 32 * TT + (size_t)(t >> 5) * TT + (t & 31);
    const float4* srcV = g_vp + (size_t)bh * 512 * 128 + (size_t)(t >> 7) * 128 + (t & 127);
    float* dstK0 = sm + ((t >> 5) * 34 + (t & 31)) * 4;
    float* dstV0 = sm + A_VS_OFF + ((t >> 7) * 130 + (t & 127)) * 4;
    uint32_t wstage = 0;   // toggling stage for writes

    auto issue_tile = [&]() {
        float* Kst = dstK0 + wstage * A_KS_STF;
        float* Vst = dstV0 + wstage * A_VS_STF;
        #pragma unroll
        for (int i = 0; i < 8; i++)
            cp16s(smem_u32(Kst + i * (4 * 34 * 4)), srcK + (size_t)(4 * i) * TT);
        #pragma unroll
        for (int i = 0; i < 8; i++)
            cp16s(smem_u32(Vst + i * (130 * 4)), srcV + i * 128);
        cp_commit();
        srcK += 32;
        srcV += 1024;
        wstage ^= 1;
    };

    const int nkt = 2 * qt + 2;
    issue_tile();

    for (int kt = 0; kt < nkt; kt++) {
        const int s = kt & 1;
        __syncthreads();
        if (kt + 1 < nkt) issue_tile();
        cp_wait<1>();
        __syncthreads();

        float sacc[4][4];
        #pragma unroll
        for (int ni = 0; ni < 4; ni++)
            #pragma unroll
            for (int r = 0; r < 4; r++) sacc[ni][r] = 0.0f;

        const float4* Kb4 = (const float4*)(sm + s * A_KS_STF);
        #pragma unroll
        for (int kg = 0; kg < 8; kg++) {
            const float4* Krow = Kb4 + (kg * 4 + tg) * 34;
            #pragma unroll
            for (int ni = 0; ni < 4; ni++) {
                float4 bv = Krow[ni * 8 + g];
                mma_tf32(sacc[ni], qf[2 * kg][0], qf[2 * kg][1], qf[2 * kg][2], qf[2 * kg][3],
                         FU(bv.x), FU(bv.y));
                mma_tf32(sacc[ni], qf[2 * kg + 1][0], qf[2 * kg + 1][1], qf[2 * kg + 1][2], qf[2 * kg + 1][3],
                         FU(bv.z), FU(bv.w));
            }
        }

        const int r0 = qbase + w * 16 + g;
        const int r1 = r0 + 8;
        float rm0 = -1e30f, rm1 = -1e30f;
        if (kt >= 2 * qt) {
            const int kb = kt * 32;
            #pragma unroll
            for (int ni = 0; ni < 4; ni++) {
                const int c0 = kb + ni * 8 + 2 * tg;
                float v0 = sacc[ni][0] * scale; if (c0     > r0) v0 = -1e30f;
                float v1 = sacc[ni][1] * scale; if (c0 + 1 > r0) v1 = -1e30f;
                float v2 = sacc[ni][2] * scale; if (c0     > r1) v2 = -1e30f;
                float v3 = sacc[ni][3] * scale; if (c0 + 1 > r1) v3 = -1e30f;
                sacc[ni][0] = v0; sacc[ni][1] = v1; sacc[ni][2] = v2; sacc[ni][3] = v3;
                rm0 = fmaxf(rm0, fmaxf(v0, v1));
                rm1 = fmaxf(rm1, fmaxf(v2, v3));
            }
        } else {
            #pragma unroll
            for (int ni = 0; ni < 4; ni++) {
                float v0 = sacc[ni][0] * scale;
                float v1 = sacc[ni][1] * scale;
                float v2 = sacc[ni][2] * scale;
                float v3 = sacc[ni][3] * scale;
                sacc[ni][0] = v0; sacc[ni][1] = v1; sacc[ni][2] = v2; sacc[ni][3] = v3;
                rm0 = fmaxf(rm0, fmaxf(v0, v1));
                rm1 = fmaxf(rm1, fmaxf(v2, v3));
            }
        }
        rm0 = fmaxf(rm0, __shfl_xor_sync(0xffffffffu, rm0, 1));
        rm0 = fmaxf(rm0, __shfl_xor_sync(0xffffffffu, rm0, 2));
        rm1 = fmaxf(rm1, __shfl_xor_sync(0xffffffffu, rm1, 1));
        rm1 = fmaxf(rm1, __shfl_xor_sync(0xffffffffu, rm1, 2));

        const float mn0 = fmaxf(m0, rm0);
        const float mn1 = fmaxf(m1, rm1);
        const float f0 = __expf(m0 - mn0);
        const float f1 = __expf(m1 - mn1);
        m0 = mn0; m1 = mn1;

        float ps0 = 0.0f, ps1 = 0.0f;
        #pragma unroll
        for (int ni = 0; ni < 4; ni++) {
            float p0 = __expf(sacc[ni][0] - mn0);
            float p1 = __expf(sacc[ni][1] - mn0);
            float p2 = __expf(sacc[ni][2] - mn1);
            float p3 = __expf(sacc[ni][3] - mn1);
            sacc[ni][0] = p0; sacc[ni][1] = p1; sacc[ni][2] = p2; sacc[ni][3] = p3;
            ps0 += p0 + p1;
            ps1 += p2 + p3;
        }
        ps0 += __shfl_xor_sync(0xffffffffu, ps0, 1);
        ps0 += __shfl_xor_sync(0xffffffffu, ps0, 2);
        ps1 += __shfl_xor_sync(0xffffffffu, ps1, 1);
        ps1 += __shfl_xor_sync(0xffffffffu, ps1, 2);
        l0 = l0 * f0 + ps0;
        l1 = l1 * f1 + ps1;

        #pragma unroll
        for (int ni = 0; ni < 16; ni++) {
            oacc[ni][0] *= f0; oacc[ni][1] *= f0;
            oacc[ni][2] *= f1; oacc[ni][3] *= f1;
        }

        const int pq = w * 16 + g;
        #pragma unroll
        for (int ni = 0; ni < 4; ni++) {
            *(float2*)&Ps[pq * LDPK + ni * 8 + 2 * tg]       = make_float2(sacc[ni][0], sacc[ni][1]);
            *(float2*)&Ps[(pq + 8) * LDPK + ni * 8 + 2 * tg] = make_float2(sacc[ni][2], sacc[ni][3]);
        }
        __syncwarp();

        const float4* Vb4 = (const float4*)(sm + A_VS_OFF + s * A_VS_STF);
        #pragma unroll
        for (int kg2 = 0; kg2 < 2; kg2++) {
            uint32_t ha[2][4];
            #pragma unroll
            for (int hh = 0; hh < 2; hh++) {
                const int ks2 = 2 * kg2 + hh;
                ha[hh][0] = f2tf(Ps[pq * LDPK + ks2 * 8 + tg]);
                ha[hh][1] = f2tf(Ps[(pq + 8) * LDPK + ks2 * 8 + tg]);
                ha[hh][2] = f2tf(Ps[pq * LDPK + ks2 * 8 + tg + 4]);
                ha[hh][3] = f2tf(Ps[(pq + 8) * LDPK + ks2 * 8 + tg + 4]);
            }
            const float4* Vrow = Vb4 + (kg2 * 4 + tg) * 130;
            #pragma unroll
            for (int ni = 0; ni < 16; ni++) {
                float4 vv = Vrow[ni * 8 + g];
                mma_tf32(oacc[ni], ha[0][0], ha[0][1], ha[0][2], ha[0][3], FU(vv.x), FU(vv.y));
                mma_tf32(oacc[ni], ha[1][0], ha[1][1], ha[1][2], ha[1][3], FU(vv.z), FU(vv.w));
            }
        }
    }

    // ---- epilogue: O/l -> Ps (tf32-rounded) -> g_ap packed ----
    const float il0 = 1.0f / l0;
    const float il1 = 1.0f / l1;
    const int lr0 = w * 16 + g;
    const int lr1 = lr0 + 8;
    __syncthreads();
    #pragma unroll
    for (int ni = 0; ni < 16; ni++) {
        const int lc = ni * 8 + 2 * tg;
        Ps[lr0 * LDPK + lc]     = tfr(oacc[ni][0] * il0);
        Ps[lr0 * LDPK + lc + 1] = tfr(oacc[ni][1] * il0);
        Ps[lr1 * LDPK + lc]     = tfr(oacc[ni][2] * il1);
        Ps[lr1 * LDPK + lc + 1] = tfr(oacc[ni][3] * il1);
    }
    __syncthreads();

    float4* ap4 = (float4*)g_ap;
    const size_t mrow0 = rowbase + qbase;
    #pragma unroll
    for (int i = 0; i < 16; i++) {
        int idx = t + (i << 7);       // 2048 cells = 32 ck x 64 m
        int ck  = idx >> 6;
        int m   = idx & 63;
        int kb  = (ck >> 2) * 16 + (ck & 3);
        float4 o = make_float4(Ps[m * LDPK + kb],     Ps[m * LDPK + kb + 4],
                               Ps[m * LDPK + kb + 8], Ps[m * LDPK + kb + 12]);
        ap4[(size_t)(32 * h + ck) * MROWS + mrow0 + m] = o;
    }
}

// ---------------- launch ----------------
extern "C" void kernel_launch(void* const* d_in, const int* in_sizes, int n_in,
                              void* d_out, int out_size)
{
    const float* x    = (const float*)d_in[0];
    const float* Wkqv = (const float*)d_in[1];
    const float* bkqv = (const float*)d_in[2];
    const float* Wo   = (const float*)d_in[3];
    const float* bo   = (const float*)d_in[4];
    float* out = (float*)d_out;

    float *kqv, *xp, *wkp, *wop, *ap, *ct, *st;
    cudaGetSymbolAddress((void**)&kqv, g_kqv);
    cudaGetSymbolAddress((void**)&xp,  g_xp);
    cudaGetSymbolAddress((void**)&wkp, g_wkp);
    cudaGetSymbolAddress((void**)&wop, g_wop);
    cudaGetSymbolAddress((void**)&ap,  g_ap);
    cudaGetSymbolAddress((void**)&ct,  g_cos);
    cudaGetSymbolAddress((void**)&st,  g_sin);

    cudaFuncSetAttribute(gemm_packed_kernel, cudaFuncAttributeMaxDynamicSharedMemorySize, GEMM_SMEM);
    cudaFuncSetAttribute(attn_mma_kernel,    cudaFuncAttributeMaxDynamicSharedMemorySize, ATT_SMEM);

    // launch order: attn at index 5 for ncu capture (-s 5 -c 1)
    trig_kernel<<<(TT * 64) / 256, 256>>>(ct, st);                               // 0
    packA_kernel<<<dim3(DD / 64, MROWS / 32), 256>>>(x, (float4*)xp, MROWS, DD); // 1
    packB_kernel<<<(DD / 4 * N3 + 255) / 256, 256>>>(Wkqv, (float4*)wkp, DD, N3);// 2
    gemm_packed_kernel<<<dim3(N3 / 128, MROWS / 128), 256, GEMM_SMEM>>>(         // 3
        (const float4*)xp, (const float4*)wkp, bkqv, kqv, MROWS, N3, DD, 1, ct, st);
    packB_kernel<<<(DD / 4 * DD + 255) / 256, 256>>>(Wo, (float4*)wop, DD, DD);  // 4
    attn_mma_kernel<<<dim3(TT / 64, BB * HH), 128, ATT_SMEM>>>();                // 5 <- profiled
    gemm_packed_kernel<<<dim3(DD / 128, MROWS / 128), 256, GEMM_SMEM>>>(         // 6
        (const float4*)ap, (const float4*)wop, bo, out, MROWS, DD, DD, 0, ct, st);
}

// round 15
// speedup vs baseline: 1.0915x; 1.0550x over previous
#include <cuda_runtime.h>
#include <math.h>
#include <stdint.h>

#define BB    2
#define TT    2048
#define DD    2048
#define HH    16
#define DK    128
#define N3    (3*DD)
#define MROWS (BB*TT)   // 4096

// ---------------- scratch (device globals; no allocation allowed) ----------------
__device__ float g_kqv[(size_t)MROWS * N3];    // q section used (k/v go packed)
__device__ float g_xp[(size_t)MROWS * DD];     // x packed (tf32)   [ck][M] float4 cells
__device__ float g_wkp[(size_t)DD * N3];       // Wkqv packed       [ck][N] float4 cells
__device__ float g_wop[(size_t)DD * DD];       // Wo packed
__device__ float g_ap[(size_t)MROWS * DD];     // attn out packed (written by attention)
__device__ float4 g_kp[(size_t)32 * 32 * TT];    // K frag-packed: [bh][ck d-cell][key]
__device__ float4 g_vp[(size_t)32 * 512 * 128];  // V frag-packed: [bh][ckv key-cell][d]
__device__ float g_cos[TT * 64];
__device__ float g_sin[TT * 64];

// ---------------- PTX helpers ----------------
__device__ __forceinline__ uint32_t smem_u32(const void* p) {
    return (uint32_t)__cvta_generic_to_shared(p);
}
__device__ __forceinline__ void cp16s(uint32_t dst, const void* src) {
    asm volatile("cp.async.cg.shared.global [%0], [%1], 16;\n" :: "r"(dst), "l"(src));
}
__device__ __forceinline__ void cp_commit() {
    asm volatile("cp.async.commit_group;\n");
}
template<int N>
__device__ __forceinline__ void cp_wait() {
    asm volatile("cp.async.wait_group %0;\n" :: "n"(N));
}
__device__ __forceinline__ uint32_t f2tf(float f) {
    uint32_t r;
    asm("cvt.rna.tf32.f32 %0, %1;" : "=r"(r) : "f"(f));
    return r;
}
__device__ __forceinline__ float tfr(float f) {
    return __uint_as_float(f2tf(f));
}
__device__ __forceinline__ void mma_tf32(float c[4],
                                         uint32_t a0, uint32_t a1, uint32_t a2, uint32_t a3,
                                         uint32_t b0, uint32_t b1) {
    asm volatile(
        "mma.sync.aligned.m16n8k8.row.col.f32.tf32.tf32.f32 "
        "{%0,%1,%2,%3}, {%4,%5,%6,%7}, {%8,%9}, {%0,%1,%2,%3};\n"
        : "+f"(c[0]), "+f"(c[1]), "+f"(c[2]), "+f"(c[3])
        : "r"(a0), "r"(a1), "r"(a2), "r"(a3), "r"(b0), "r"(b1));
}
#define FU(x) __float_as_uint(x)

// ---------------- fused prep: trig tables + packA(x) + packB(Wkqv) + packB(Wo) ----------------
// flat grid: [0,512) trig | [512,4608) packA | [4608,16896) packB wk | [16896,20992) packB wo
#define PREP_TRIG   512
#define PREP_PA     4096
#define PREP_PBK    12288
#define PREP_PBO    4096
#define PREP_GRID   (PREP_TRIG + PREP_PA + PREP_PBK + PREP_PBO)

__global__ void prep_kernel(const float* __restrict__ x,
                            const float* __restrict__ Wkqv,
                            const float* __restrict__ Wo,
                            float4* __restrict__ xp,
                            float4* __restrict__ wkp,
                            float4* __restrict__ wop,
                            float* __restrict__ ct, float* __restrict__ st)
{
    __shared__ float tile[32][65];
    const int bid = blockIdx.x;
    const int t   = threadIdx.x;

    if (bid < PREP_TRIG) {
        // ---- RoPE trig tables ----
        int idx = bid * 256 + t;
        int tpos = idx >> 6;
        int p    = idx & 63;
        float invf = (float)pow(10000.0, -(double)p / 64.0);
        float ang = (float)tpos * invf;
        float s, c;
        sincosf(ang, &s, &c);
        ct[idx] = c;
        st[idx] = s;
    } else if (bid < PREP_TRIG + PREP_PA) {
        // ---- packA(x): 32 k-blocks x 128 m-blocks ----
        const int bb = bid - PREP_TRIG;
        const int k0 = (bb & 31) * 64;
        const int m0 = (bb >> 5) * 32;
        const int K = DD, Mt = MROWS;
        #pragma unroll
        for (int i = 0; i < 2; i++) {
            int u = t + (i << 8);
            int m = u >> 4;
            int kc = u & 15;
            float4 v = *(const float4*)&x[(size_t)(m0 + m) * K + k0 + kc * 4];
            tile[m][kc * 4 + 0] = v.x;
            tile[m][kc * 4 + 1] = v.y;
            tile[m][kc * 4 + 2] = v.z;
            tile[m][kc * 4 + 3] = v.w;
        }
        __syncthreads();
        #pragma unroll
        for (int i = 0; i < 2; i++) {
            int u  = t + (i << 8);
            int ck = u >> 5;
            int m  = u & 31;
            int kg = ck >> 2, tg = ck & 3;
            int kb = kg * 16 + tg;
            float4 v;
            v.x = tfr(tile[m][kb]);
            v.y = tfr(tile[m][kb + 4]);
            v.z = tfr(tile[m][kb + 8]);
            v.w = tfr(tile[m][kb + 12]);
            xp[(size_t)((k0 / 16 + kg) * 4 + tg) * Mt + m0 + m] = v;
        }
    } else {
        // ---- packB for Wkqv or Wo ----
        const float* W;
        float4* out;
        int N, idx;
        if (bid < PREP_TRIG + PREP_PA + PREP_PBK) {
            W = Wkqv; out = wkp; N = N3;
            idx = (bid - (PREP_TRIG + PREP_PA)) * 256 + t;
        } else {
            W = Wo; out = wop; N = DD;
            idx = (bid - (PREP_TRIG + PREP_PA + PREP_PBK)) * 256 + t;
        }
        int ck = idx / N;
        int n  = idx - ck * N;
        int kg = ck >> 2, tg = ck & 3;
        int kb = kg * 16 + tg;
        float4 v;
        v.x = tfr(W[(size_t)kb * N + n]);
        v.y = tfr(W[(size_t)(kb + 4) * N + n]);
        v.z = tfr(W[(size_t)(kb + 8) * N + n]);
        v.w = tfr(W[(size_t)(kb + 12) * N + n]);
        out[(size_t)ck * N + n] = v;
    }
}

// ---------------- packed TF32 GEMM: CTA 128x128, warp 64x32, BK=32/stage, 3 stages ----------------
#define HALF_CELLS  1040                     // 8*130
#define STAGE_BYTES (2 * HALF_CELLS * 16)    // 33280
#define GEMM_SMEM   (3 * STAGE_BYTES)        // 99840  (>= 128*133*4 for S bounce)
#define LDS_S 133

__global__ __launch_bounds__(256, 2)
void gemm_packed_kernel(const float4* __restrict__ Ap, const float4* __restrict__ Bp,
                        const float* __restrict__ bias, float* __restrict__ C,
                        int Mt, int Nt, int K, int mode,
                        const float* __restrict__ ct, const float* __restrict__ st)
{
    extern __shared__ char smx[];
    const uint32_t sb = smem_u32(smx);
    const int t    = threadIdx.x;
    const int wid  = t >> 5;
    const int lane = t & 31;
    const int g    = lane >> 2;
    const int tg   = lane & 3;
    const int wm   = wid & 1;
    const int wn   = wid >> 1;
    const int rowBase = blockIdx.y * 128;
    const int colBase = blockIdx.x * 128;

    float acc[4][4][4];
    #pragma unroll
    for (int mi = 0; mi < 4; mi++)
        #pragma unroll
        for (int ni = 0; ni < 4; ni++)
            #pragma unroll
            for (int r = 0; r < 4; r++) acc[mi][ni][r] = 0.0f;

    const int NK = K / 32;

    // ---- incremental-pointer loader ----
    const float4* srcA = Ap + (size_t)(t >> 7) * Mt + rowBase + (t & 127);
    const float4* srcB = Bp + (size_t)(t >> 7) * Nt + colBase + (t & 127);
    const uint32_t dstA0 = sb + (((t >> 7) * 130 + (t & 127)) << 4);
    const uint32_t dstB0 = dstA0 + HALF_CELLS * 16;
    uint32_t soff = 0;

    auto issue = [&]() {
        #pragma unroll
        for (int i = 0; i < 4; i++) {
            cp16s(dstA0 + soff + i * (2 * 130 * 16), srcA + (size_t)(2 * i) * Mt);
            cp16s(dstB0 + soff + i * (2 * 130 * 16), srcB + (size_t)(2 * i) * Nt);
        }
        cp_commit();
        srcA += (size_t)8 * Mt;
        srcB += (size_t)8 * Nt;
        soff = (soff == 2 * STAGE_BYTES) ? 0 : soff + STAGE_BYTES;
    };

    issue();
    issue();

    uint32_t stgoff = 0;
    for (int kt = 0; kt < NK; kt++) {
        cp_wait<1>();
        __syncthreads();
        if (kt + 2 < NK) issue();

        const float* Stg = (const float*)(smx + stgoff);
        stgoff = (stgoff == 2 * STAGE_BYTES) ? 0 : stgoff + STAGE_BYTES;

        #pragma unroll
        for (int sub = 0; sub < 2; sub++) {
            const float* Asl = Stg + (sub * 4 + tg) * 130 * 4;
            const float* Bsl = Stg + (HALF_CELLS + (sub * 4 + tg) * 130) * 4;

            float4 A0[4], A1[4], Bv[4];
            #pragma unroll
            for (int mi = 0; mi < 4; mi++) {
                const int mr = wm * 64 + mi * 16 + g;
                A0[mi] = *(const float4*)&Asl[mr * 4];
                A1[mi] = *(const float4*)&Asl[(mr + 8) * 4];
            }
            #pragma unroll
            for (int ni = 0; ni < 4; ni++)
                Bv[ni] = *(const float4*)&Bsl[(wn * 32 + ni * 8 + g) * 4];

            #pragma unroll
            for (int mi = 0; mi < 4; mi++)
                #pragma unroll
                for (int ni = 0; ni < 4; ni++) {
                    mma_tf32(acc[mi][ni], FU(A0[mi].x), FU(A1[mi].x), FU(A0[mi].y), FU(A1[mi].y),
                             FU(Bv[ni].x), FU(Bv[ni].y));
                    mma_tf32(acc[mi][ni], FU(A0[mi].z), FU(A1[mi].z), FU(A0[mi].w), FU(A1[mi].w),
                             FU(Bv[ni].z), FU(Bv[ni].w));
                }
        }
    }
    cp_wait<0>();

    const int sect = (mode == 1) ? (colBase >> 11) : -1;

    if (mode == 0 || sect == 1) {
        // ---- plain epilogue: bias (+rope+tfr for q section), store to C ----
        #pragma unroll
        for (int mi = 0; mi < 4; mi++) {
            const int r0 = rowBase + wm * 64 + mi * 16 + g;
            const int r1 = r0 + 8;
            #pragma unroll
            for (int ni = 0; ni < 4; ni++) {
                const int c = colBase + wn * 32 + ni * 8 + tg * 2;
                const float2 b2 = *(const float2*)&bias[c];
                float v0 = acc[mi][ni][0] + b2.x;
                float v1 = acc[mi][ni][1] + b2.y;
                float v2 = acc[mi][ni][2] + b2.x;
                float v3 = acc[mi][ni][3] + b2.y;
                if (sect == 1) {
                    const int pj = (c & 127) >> 1;
                    const float c0 = ct[(r0 & (TT - 1)) * 64 + pj];
                    const float s0 = st[(r0 & (TT - 1)) * 64 + pj];
                    const float c1 = ct[(r1 & (TT - 1)) * 64 + pj];
                    const float s1 = st[(r1 & (TT - 1)) * 64 + pj];
                    float e0 = v0 * c0 - v1 * s0, o0 = v0 * s0 + v1 * c0;
                    float e1 = v2 * c1 - v3 * s1, o1 = v2 * s1 + v3 * c1;
                    v0 = tfr(e0); v1 = tfr(o0); v2 = tfr(e1); v3 = tfr(o1);
                }
                *(float2*)&C[(size_t)r0 * Nt + c] = make_float2(v0, v1);
                *(float2*)&C[(size_t)r1 * Nt + c] = make_float2(v2, v3);
            }
        }
    } else {
        // ---- k (sect 0, rope) / v (sect 2) : bounce via smem, store packed ----
        float* S = (float*)smx;   // [128][LDS_S], scalar access only
        __syncthreads();
        #pragma unroll
        for (int mi = 0; mi < 4; mi++) {
            const int lr0 = wm * 64 + mi * 16 + g;
            const int lr1 = lr0 + 8;
            const int r0 = rowBase + lr0;
            const int r1 = rowBase + lr1;
            #pragma unroll
            for (int ni = 0; ni < 4; ni++) {
                const int lc = wn * 32 + ni * 8 + tg * 2;
                const int c  = colBase + lc;
                const float2 b2 = *(const float2*)&bias[c];
                float v0 = acc[mi][ni][0] + b2.x;
                float v1 = acc[mi][ni][1] + b2.y;
                float v2 = acc[mi][ni][2] + b2.x;
                float v3 = acc[mi][ni][3] + b2.y;
                if (sect == 0) {
                    const int pj = (c & 127) >> 1;
                    const float c0 = ct[(r0 & (TT - 1)) * 64 + pj];
                    const float s0 = st[(r0 & (TT - 1)) * 64 + pj];
                    const float c1 = ct[(r1 & (TT - 1)) * 64 + pj];
                    const float s1 = st[(r1 & (TT - 1)) * 64 + pj];
                    float e0 = v0 * c0 - v1 * s0, o0 = v0 * s0 + v1 * c0;
                    float e1 = v2 * c1 - v3 * s1, o1 = v2 * s1 + v3 * c1;
                    v0 = e0; v1 = o0; v2 = e1; v3 = o1;
                }
                S[lr0 * LDS_S + lc]     = tfr(v0);
                S[lr0 * LDS_S + lc + 1] = tfr(v1);
                S[lr1 * LDS_S + lc]     = tfr(v2);
                S[lr1 * LDS_S + lc + 1] = tfr(v3);
            }
        }
        __syncthreads();

        const int head = (colBase & 2047) >> 7;
        const int bh   = (rowBase >> 11) * 16 + head;
        const int keybase = rowBase & 2047;
        if (sect == 0) {
            #pragma unroll
            for (int i = 0; i < 16; i++) {
                int idx = t + (i << 8);
                int ck  = idx >> 7;
                int key = idx & 127;
                int kb  = (ck >> 2) * 16 + (ck & 3);
                float4 o = make_float4(S[key * LDS_S + kb],     S[key * LDS_S + kb + 4],
                                       S[key * LDS_S + kb + 8], S[key * LDS_S + kb + 12]);
                g_kp[((size_t)bh * 32 + ck) * TT + keybase + key] = o;
            }
        } else {
            #pragma unroll
            for (int i = 0; i < 16; i++) {
                int idx = t + (i << 8);
                int cl  = idx >> 7;
                int d   = idx & 127;
                int kgl = cl >> 2, tgv = cl & 3;
                int kbv = kgl * 16 + tgv;
                float4 o = make_float4(S[kbv * LDS_S + d],        S[(kbv + 4) * LDS_S + d],
                                       S[(kbv + 8) * LDS_S + d],  S[(kbv + 12) * LDS_S + d]);
                int ckvG = (keybase / 16 + kgl) * 4 + tgv;
                g_vp[((size_t)bh * 512 + ckvG) * 128 + d] = o;
            }
        }
    }
}

// ---------------- Flash attention: 64q CTAs, 128 thr, 32-key tiles, 2 CTAs/SM ----------------
#define A_KS_STF (32 * 34 * 4)               // 4352 floats/stage
#define A_VS_STF (8 * 130 * 4)               // 4160 floats/stage
#define A_VS_OFF (2 * A_KS_STF)              // 8704
#define A_PS_OFF (A_VS_OFF + 2 * A_VS_STF)   // 17024
#define LDPK 132                             // 16B-aligned rows
#define ATT_SMEM ((A_PS_OFF + 64 * LDPK) * 4)   // 101888 B -> 2 CTAs/SM

__global__ __launch_bounds__(128, 2)
void attn_mma_kernel()
{
    extern __shared__ float sm[];
    float* Ps = sm + A_PS_OFF;

    const int t    = threadIdx.x;
    const int lane = t & 31;
    const int w    = t >> 5;
    const int g    = lane >> 2;
    const int tg   = lane & 3;
    const int bh = blockIdx.y;
    const int b  = bh >> 4;
    const int h  = bh & 15;
    const int qt = (int)gridDim.x - 1 - (int)blockIdx.x;
    const int qbase = qt * 64;
    const size_t rowbase = (size_t)b * TT;
    const int hoff = h * DK;
    const float scale = 0.08838834764831845f;

    for (int u = t; u < 64 * 32; u += 128) {
        int qi = u >> 5;
        int c  = u & 31;
        float4 v = *(const float4*)&g_kqv[(rowbase + qbase + qi) * N3 + DD + hoff + c * 4];
        *(float4*)&Ps[qi * LDPK + c * 4] = v;
    }
    __syncthreads();
    const int qr = w * 16 + g;
    uint32_t qf[16][4];
    #pragma unroll
    for (int ks = 0; ks < 16; ks++) {
        qf[ks][0] = *(const uint32_t*)&Ps[qr * LDPK + ks * 8 + tg];
        qf[ks][1] = *(const uint32_t*)&Ps[(qr + 8) * LDPK + ks * 8 + tg];
        qf[ks][2] = *(const uint32_t*)&Ps[qr * LDPK + ks * 8 + tg + 4];
        qf[ks][3] = *(const uint32_t*)&Ps[(qr + 8) * LDPK + ks * 8 + tg + 4];
    }
    __syncthreads();

    float oacc[16][4];
    #pragma unroll
    for (int ni = 0; ni < 16; ni++)
        #pragma unroll
        for (int r = 0; r < 4; r++) oacc[ni][r] = 0.0f;
    float m0 = -1e30f, m1 = -1e30f, l0 = 0.0f, l1 = 0.0f;

    // ---- incremental-pointer tile loader ----
    const float4* srcK = g_kp + (size_t)bh * 32 * TT + (size_t)(t >> 5) * TT + (t & 31);
    const float4* srcV = g_vp + (size_t)bh * 512 * 128 + (size_t)(t >> 7) * 128 + (t & 127);
    float* dstK0 = sm + ((t >> 5) * 34 + (t & 31)) * 4;
    float* dstV0 = sm + A_VS_OFF + ((t >> 7) * 130 + (t & 127)) * 4;
    uint32_t wstage = 0;

    auto issue_tile = [&]() {
        float* Kst = dstK0 + wstage * A_KS_STF;
        float* Vst = dstV0 + wstage * A_VS_STF;
        #pragma unroll
        for (int i = 0; i < 8; i++)
            cp16s(smem_u32(Kst + i * (4 * 34 * 4)), srcK + (size_t)(4 * i) * TT);
        #pragma unroll
        for (int i = 0; i < 8; i++)
            cp16s(smem_u32(Vst + i * (130 * 4)), srcV + i * 128);
        cp_commit();
        srcK += 32;
        srcV += 1024;
        wstage ^= 1;
    };

    const int nkt = 2 * qt + 2;
    issue_tile();

    for (int kt = 0; kt < nkt; kt++) {
        const int s = kt & 1;
        __syncthreads();
        if (kt + 1 < nkt) issue_tile();
        cp_wait<1>();
        __syncthreads();

        float sacc[4][4];
        #pragma unroll
        for (int ni = 0; ni < 4; ni++)
            #pragma unroll
            for (int r = 0; r < 4; r++) sacc[ni][r] = 0.0f;

        const float4* Kb4 = (const float4*)(sm + s * A_KS_STF);
        #pragma unroll
        for (int kg = 0; kg < 8; kg++) {
            const float4* Krow = Kb4 + (kg * 4 + tg) * 34;
            #pragma unroll
            for (int ni = 0; ni < 4; ni++) {
                float4 bv = Krow[ni * 8 + g];
                mma_tf32(sacc[ni], qf[2 * kg][0], qf[2 * kg][1], qf[2 * kg][2], qf[2 * kg][3],
                         FU(bv.x), FU(bv.y));
                mma_tf32(sacc[ni], qf[2 * kg + 1][0], qf[2 * kg + 1][1], qf[2 * kg + 1][2], qf[2 * kg + 1][3],
                         FU(bv.z), FU(bv.w));
            }
        }

        const int r0 = qbase + w * 16 + g;
        const int r1 = r0 + 8;
        float rm0 = -1e30f, rm1 = -1e30f;
        if (kt >= 2 * qt) {
            const int kb = kt * 32;
            #pragma unroll
            for (int ni = 0; ni < 4; ni++) {
                const int c0 = kb + ni * 8 + 2 * tg;
                float v0 = sacc[ni][0] * scale; if (c0     > r0) v0 = -1e30f;
                float v1 = sacc[ni][1] * scale; if (c0 + 1 > r0) v1 = -1e30f;
                float v2 = sacc[ni][2] * scale; if (c0     > r1) v2 = -1e30f;
                float v3 = sacc[ni][3] * scale; if (c0 + 1 > r1) v3 = -1e30f;
                sacc[ni][0] = v0; sacc[ni][1] = v1; sacc[ni][2] = v2; sacc[ni][3] = v3;
                rm0 = fmaxf(rm0, fmaxf(v0, v1));
                rm1 = fmaxf(rm1, fmaxf(v2, v3));
            }
        } else {
            #pragma unroll
            for (int ni = 0; ni < 4; ni++) {
                float v0 = sacc[ni][0] * scale;
                float v1 = sacc[ni][1] * scale;
                float v2 = sacc[ni][2] * scale;
                float v3 = sacc[ni][3] * scale;
                sacc[ni][0] = v0; sacc[ni][1] = v1; sacc[ni][2] = v2; sacc[ni][3] = v3;
                rm0 = fmaxf(rm0, fmaxf(v0, v1));
                rm1 = fmaxf(rm1, fmaxf(v2, v3));
            }
        }
        rm0 = fmaxf(rm0, __shfl_xor_sync(0xffffffffu, rm0, 1));
        rm0 = fmaxf(rm0, __shfl_xor_sync(0xffffffffu, rm0, 2));
        rm1 = fmaxf(rm1, __shfl_xor_sync(0xffffffffu, rm1, 1));
        rm1 = fmaxf(rm1, __shfl_xor_sync(0xffffffffu, rm1, 2));

        const float mn0 = fmaxf(m0, rm0);
        const float mn1 = fmaxf(m1, rm1);
        const float f0 = __expf(m0 - mn0);
        const float f1 = __expf(m1 - mn1);
        m0 = mn0; m1 = mn1;

        float ps0 = 0.0f, ps1 = 0.0f;
        #pragma unroll
        for (int ni = 0; ni < 4; ni++) {
            float p0 = __expf(sacc[ni][0] - mn0);
            float p1 = __expf(sacc[ni][1] - mn0);
            float p2 = __expf(sacc[ni][2] - mn1);
            float p3 = __expf(sacc[ni][3] - mn1);
            sacc[ni][0] = p0; sacc[ni][1] = p1; sacc[ni][2] = p2; sacc[ni][3] = p3;
            ps0 += p0 + p1;
            ps1 += p2 + p3;
        }
        ps0 += __shfl_xor_sync(0xffffffffu, ps0, 1);
        ps0 += __shfl_xor_sync(0xffffffffu, ps0, 2);
        ps1 += __shfl_xor_sync(0xffffffffu, ps1, 1);
        ps1 += __shfl_xor_sync(0xffffffffu, ps1, 2);
        l0 = l0 * f0 + ps0;
        l1 = l1 * f1 + ps1;

        #pragma unroll
        for (int ni = 0; ni < 16; ni++) {
            oacc[ni][0] *= f0; oacc[ni][1] *= f0;
            oacc[ni][2] *= f1; oacc[ni][3] *= f1;
        }

        const int pq = w * 16 + g;
        #pragma unroll
        for (int ni = 0; ni < 4; ni++) {
            *(float2*)&Ps[pq * LDPK + ni * 8 + 2 * tg]       = make_float2(sacc[ni][0], sacc[ni][1]);
            *(float2*)&Ps[(pq + 8) * LDPK + ni * 8 + 2 * tg] = make_float2(sacc[ni][2], sacc[ni][3]);
        }
        __syncwarp();

        const float4* Vb4 = (const float4*)(sm + A_VS_OFF + s * A_VS_STF);
        #pragma unroll
        for (int kg2 = 0; kg2 < 2; kg2++) {
            uint32_t ha[2][4];
            #pragma unroll
            for (int hh = 0; hh < 2; hh++) {
                const int ks2 = 2 * kg2 + hh;
                ha[hh][0] = f2tf(Ps[pq * LDPK + ks2 * 8 + tg]);
                ha[hh][1] = f2tf(Ps[(pq + 8) * LDPK + ks2 * 8 + tg]);
                ha[hh][2] = f2tf(Ps[pq * LDPK + ks2 * 8 + tg + 4]);
                ha[hh][3] = f2tf(Ps[(pq + 8) * LDPK + ks2 * 8 + tg + 4]);
            }
            const float4* Vrow = Vb4 + (kg2 * 4 + tg) * 130;
            #pragma unroll
            for (int ni = 0; ni < 16; ni++) {
                float4 vv = Vrow[ni * 8 + g];
                mma_tf32(oacc[ni], ha[0][0], ha[0][1], ha[0][2], ha[0][3], FU(vv.x), FU(vv.y));
                mma_tf32(oacc[ni], ha[1][0], ha[1][1], ha[1][2], ha[1][3], FU(vv.z), FU(vv.w));
            }
        }
    }

    // ---- epilogue: O/l -> Ps (tf32-rounded) -> g_ap packed ----
    const float il0 = 1.0f / l0;
    const float il1 = 1.0f / l1;
    const int lr0 = w * 16 + g;
    const int lr1 = lr0 + 8;
    __syncthreads();
    #pragma unroll
    for (int ni = 0; ni < 16; ni++) {
        const int lc = ni * 8 + 2 * tg;
        Ps[lr0 * LDPK + lc]     = tfr(oacc[ni][0] * il0);
        Ps[lr0 * LDPK + lc + 1] = tfr(oacc[ni][1] * il0);
        Ps[lr1 * LDPK + lc]     = tfr(oacc[ni][2] * il1);
        Ps[lr1 * LDPK + lc + 1] = tfr(oacc[ni][3] * il1);
    }
    __syncthreads();

    float4* ap4 = (float4*)g_ap;
    const size_t mrow0 = rowbase + qbase;
    #pragma unroll
    for (int i = 0; i < 16; i++) {
        int idx = t + (i << 7);       // 2048 cells = 32 ck x 64 m
        int ck  = idx >> 6;
        int m   = idx & 63;
        int kb  = (ck >> 2) * 16 + (ck & 3);
        float4 o = make_float4(Ps[m * LDPK + kb],     Ps[m * LDPK + kb + 4],
                               Ps[m * LDPK + kb + 8], Ps[m * LDPK + kb + 12]);
        ap4[(size_t)(32 * h + ck) * MROWS + mrow0 + m] = o;
    }
}

// ---------------- launch ----------------
extern "C" void kernel_launch(void* const* d_in, const int* in_sizes, int n_in,
                              void* d_out, int out_size)
{
    const float* x    = (const float*)d_in[0];
    const float* Wkqv = (const float*)d_in[1];
    const float* bkqv = (const float*)d_in[2];
    const float* Wo   = (const float*)d_in[3];
    const float* bo   = (const float*)d_in[4];
    float* out = (float*)d_out;

    float *kqv, *xp, *wkp, *wop, *ap, *ct, *st;
    cudaGetSymbolAddress((void**)&kqv, g_kqv);
    cudaGetSymbolAddress((void**)&xp,  g_xp);
    cudaGetSymbolAddress((void**)&wkp, g_wkp);
    cudaGetSymbolAddress((void**)&wop, g_wop);
    cudaGetSymbolAddress((void**)&ap,  g_ap);
    cudaGetSymbolAddress((void**)&ct,  g_cos);
    cudaGetSymbolAddress((void**)&st,  g_sin);

    cudaFuncSetAttribute(gemm_packed_kernel, cudaFuncAttributeMaxDynamicSharedMemorySize, GEMM_SMEM);
    cudaFuncSetAttribute(attn_mma_kernel,    cudaFuncAttributeMaxDynamicSharedMemorySize, ATT_SMEM);

    // 0) fused prep: trig + pack x + pack Wkqv + pack Wo (one launch)
    prep_kernel<<<PREP_GRID, 256>>>(x, Wkqv, Wo, (float4*)xp, (float4*)wkp,
                                    (float4*)wop, ct, st);
    // 1) QKV GEMM (fused rope; writes q plain + k/v fragment-packed)
    gemm_packed_kernel<<<dim3(N3 / 128, MROWS / 128), 256, GEMM_SMEM>>>(
        (const float4*)xp, (const float4*)wkp, bkqv, kqv, MROWS, N3, DD, 1, ct, st);
    // 2) causal flash attention (writes packed attn output)
    attn_mma_kernel<<<dim3(TT / 64, BB * HH), 128, ATT_SMEM>>>();
    // 3) out-projection GEMM
    gemm_packed_kernel<<<dim3(DD / 128, MROWS / 128), 256, GEMM_SMEM>>>(
        (const float4*)ap, (const float4*)wop, bo, out, MROWS, DD, DD, 0, ct, st);
}